// round 1
// baseline (speedup 1.0000x reference)
#include <cuda_runtime.h>

#define BATCH   4
#define SEQ     2048
#define DMODEL  1024
#define NHEADS  16
#define DK      64
#define MROWS   (BATCH * SEQ)   // 8192

// Scratch (allocation-free rule: static __device__ arrays).
__device__ float g_Q[BATCH * NHEADS * SEQ * DK];   // [B,H,S,DK] 32MB
__device__ float g_K[BATCH * NHEADS * SEQ * DK];
__device__ float g_V[BATCH * NHEADS * SEQ * DK];
__device__ float g_Ctx[BATCH * SEQ * DMODEL];      // merged heads [B,S,D] 32MB

// ---------------------------------------------------------------------------
// NT SGEMM: Y[m][n] = sum_k X[m][k] * W[n][k]   (X: MxK row-major, W: NxK row-major)
// Tile 128x128xBK16, 256 threads, 8x8 per thread.
// DEST: 0 -> g_Q (head-split), 1 -> g_K, 2 -> g_V, 3 -> Y plain [M][N], X:=g_Ctx
// ---------------------------------------------------------------------------
template <int DEST>
__global__ void __launch_bounds__(256) sgemm_nt(const float* __restrict__ X,
                                                const float* __restrict__ W,
                                                float* __restrict__ Y) {
    constexpr int K = DMODEL;
    constexpr int N = DMODEL;
    __shared__ float Xs[16][132];   // [k][m], padded
    __shared__ float Ws[16][132];   // [k][n], padded

    const int tid = threadIdx.x;
    const int tx  = tid & 15;
    const int ty  = tid >> 4;
    const int m0  = blockIdx.y * 128;
    const int n0  = blockIdx.x * 128;
    const int lr  = tid >> 2;         // 0..63
    const int lc  = (tid & 3) << 2;   // 0,4,8,12

    const float* Xp = (DEST == 3) ? (const float*)g_Ctx : X;

    float acc[8][8];
#pragma unroll
    for (int i = 0; i < 8; i++)
#pragma unroll
        for (int j = 0; j < 8; j++) acc[i][j] = 0.f;

    const float* xp0 = Xp + (size_t)(m0 + lr) * K + lc;
    const float* xp1 = Xp + (size_t)(m0 + lr + 64) * K + lc;
    const float* wp0 = W + (size_t)(n0 + lr) * K + lc;
    const float* wp1 = W + (size_t)(n0 + lr + 64) * K + lc;

    for (int k0 = 0; k0 < K; k0 += 16) {
        float4 xa = *(const float4*)(xp0 + k0);
        float4 xb = *(const float4*)(xp1 + k0);
        float4 wa = *(const float4*)(wp0 + k0);
        float4 wb = *(const float4*)(wp1 + k0);
        __syncthreads();
        Xs[lc + 0][lr] = xa.x; Xs[lc + 1][lr] = xa.y;
        Xs[lc + 2][lr] = xa.z; Xs[lc + 3][lr] = xa.w;
        Xs[lc + 0][lr + 64] = xb.x; Xs[lc + 1][lr + 64] = xb.y;
        Xs[lc + 2][lr + 64] = xb.z; Xs[lc + 3][lr + 64] = xb.w;
        Ws[lc + 0][lr] = wa.x; Ws[lc + 1][lr] = wa.y;
        Ws[lc + 2][lr] = wa.z; Ws[lc + 3][lr] = wa.w;
        Ws[lc + 0][lr + 64] = wb.x; Ws[lc + 1][lr + 64] = wb.y;
        Ws[lc + 2][lr + 64] = wb.z; Ws[lc + 3][lr + 64] = wb.w;
        __syncthreads();
#pragma unroll
        for (int k = 0; k < 16; k++) {
            float a[8], b[8];
            *(float4*)(a + 0) = *(const float4*)&Xs[k][ty * 4];
            *(float4*)(a + 4) = *(const float4*)&Xs[k][64 + ty * 4];
            *(float4*)(b + 0) = *(const float4*)&Ws[k][tx * 4];
            *(float4*)(b + 4) = *(const float4*)&Ws[k][64 + tx * 4];
#pragma unroll
            for (int i = 0; i < 8; i++)
#pragma unroll
                for (int j = 0; j < 8; j++)
                    acc[i][j] = fmaf(a[i], b[j], acc[i][j]);
        }
    }

#pragma unroll
    for (int i = 0; i < 8; i++) {
        const int m = m0 + ((i >> 2) << 6) + ty * 4 + (i & 3);
#pragma unroll
        for (int jg = 0; jg < 2; jg++) {
            const int n = n0 + jg * 64 + tx * 4;
            float4 v = make_float4(acc[i][jg * 4 + 0], acc[i][jg * 4 + 1],
                                   acc[i][jg * 4 + 2], acc[i][jg * 4 + 3]);
            if (DEST == 3) {
                *(float4*)&Y[(size_t)m * N + n] = v;
            } else {
                float* O = (DEST == 0) ? g_Q : (DEST == 1) ? g_K : g_V;
                const int b  = m >> 11;          // / SEQ
                const int s  = m & (SEQ - 1);
                const int h  = n >> 6;           // / DK
                const int dc = n & (DK - 1);
                *(float4*)&O[((size_t)(b * NHEADS + h) * SEQ + s) * DK + dc] = v;
            }
        }
    }
}

// ---------------------------------------------------------------------------
// Causal flash attention, d_k = 64. Grid: (SEQ/64, B*H). 256 threads (16x16).
// Per block: 64 query rows. Iterates key blocks kb = 0..qb (lower triangle).
// Smem: Qs [d][i], KPs [d][j] (K) reused as P [i][j], Vs [j][d]. Exactly 48KB.
// ---------------------------------------------------------------------------
__global__ void __launch_bounds__(256) attn_causal() {
    __shared__ float Qs[64][64];   // transposed Q: [d][i]
    __shared__ float KPs[64][64];  // K transposed [d][j]; later P natural [i][j]
    __shared__ float Vs[64][64];   // V natural [j][d]

    const int tid = threadIdx.x;
    const int tx  = tid & 15;
    const int ty  = tid >> 4;
    const int qb  = blockIdx.x;
    const int bh  = blockIdx.y;

    const float* Qg = g_Q + (size_t)bh * SEQ * DK;
    const float* Kg = g_K + (size_t)bh * SEQ * DK;
    const float* Vg = g_V + (size_t)bh * SEQ * DK;

    const int lr = tid >> 2;   // row 0..63
    const int c  = tid & 3;

    // Load Q tile transposed into smem.
    {
        const float* q = Qg + (size_t)(qb * 64 + lr) * DK;
#pragma unroll
        for (int qd = 0; qd < 4; qd++) {
            const int d0 = (qd * 4 + c) * 4;
            float4 v = *(const float4*)(q + d0);
            Qs[d0 + 0][lr] = v.x; Qs[d0 + 1][lr] = v.y;
            Qs[d0 + 2][lr] = v.z; Qs[d0 + 3][lr] = v.w;
        }
    }

    float m_i[4], l_i[4], acc[4][4];
#pragma unroll
    for (int i = 0; i < 4; i++) {
        m_i[i] = -1e30f; l_i[i] = 0.f;
#pragma unroll
        for (int j = 0; j < 4; j++) acc[i][j] = 0.f;
    }

    for (int kb = 0; kb <= qb; kb++) {
        __syncthreads();   // previous PV reads done before overwriting KPs/Vs
        {
            const float* kp = Kg + (size_t)(kb * 64 + lr) * DK;
            const float* vp = Vg + (size_t)(kb * 64 + lr) * DK;
#pragma unroll
            for (int qd = 0; qd < 4; qd++) {
                const int d0 = (qd * 4 + c) * 4;
                float4 kv = *(const float4*)(kp + d0);
                KPs[d0 + 0][lr] = kv.x; KPs[d0 + 1][lr] = kv.y;
                KPs[d0 + 2][lr] = kv.z; KPs[d0 + 3][lr] = kv.w;
                *(float4*)&Vs[lr][d0] = *(const float4*)(vp + d0);
            }
        }
        __syncthreads();

        // S = Q @ K^T (64x64 distributed 4x4 per thread)
        float s[4][4];
#pragma unroll
        for (int i = 0; i < 4; i++)
#pragma unroll
            for (int j = 0; j < 4; j++) s[i][j] = 0.f;

#pragma unroll 8
        for (int d = 0; d < 64; d++) {
            float4 a = *(const float4*)&Qs[d][ty * 4];
            float4 b = *(const float4*)&KPs[d][tx * 4];
            const float av[4] = {a.x, a.y, a.z, a.w};
            const float bv[4] = {b.x, b.y, b.z, b.w};
#pragma unroll
            for (int i = 0; i < 4; i++)
#pragma unroll
                for (int j = 0; j < 4; j++)
                    s[i][j] = fmaf(av[i], bv[j], s[i][j]);
        }

        const float SC = 0.125f;  // 1/sqrt(64)
#pragma unroll
        for (int i = 0; i < 4; i++)
#pragma unroll
            for (int j = 0; j < 4; j++) s[i][j] *= SC;

        if (kb == qb) {  // diagonal block: mask strictly-upper
#pragma unroll
            for (int i = 0; i < 4; i++)
#pragma unroll
                for (int j = 0; j < 4; j++)
                    if (tx * 4 + j > ty * 4 + i) s[i][j] = -1e9f;
        }

        // Online softmax. Row stats reduced across the 16 tx lanes (half-warp).
        float corr[4];
#pragma unroll
        for (int i = 0; i < 4; i++) {
            float rm = fmaxf(fmaxf(s[i][0], s[i][1]), fmaxf(s[i][2], s[i][3]));
#pragma unroll
            for (int o = 8; o; o >>= 1)
                rm = fmaxf(rm, __shfl_xor_sync(0xffffffffu, rm, o));
            const float nm = fmaxf(m_i[i], rm);
            corr[i] = __expf(m_i[i] - nm);
            m_i[i]  = nm;
            float rs = 0.f;
#pragma unroll
            for (int j = 0; j < 4; j++) {
                s[i][j] = __expf(s[i][j] - nm);
                rs += s[i][j];
            }
#pragma unroll
            for (int o = 8; o; o >>= 1)
                rs += __shfl_xor_sync(0xffffffffu, rs, o);
            l_i[i] = l_i[i] * corr[i] + rs;
#pragma unroll
            for (int j = 0; j < 4; j++) acc[i][j] *= corr[i];
        }

        __syncthreads();   // done reading KPs as K
#pragma unroll
        for (int i = 0; i < 4; i++)
            *(float4*)&KPs[ty * 4 + i][tx * 4] =
                make_float4(s[i][0], s[i][1], s[i][2], s[i][3]);
        __syncthreads();

        // acc += P @ V
#pragma unroll 4
        for (int j = 0; j < 64; j++) {
            float4 bv = *(const float4*)&Vs[j][tx * 4];
            const float b0 = bv.x, b1 = bv.y, b2 = bv.z, b3 = bv.w;
#pragma unroll
            for (int i = 0; i < 4; i++) {
                const float a = KPs[ty * 4 + i][j];
                acc[i][0] = fmaf(a, b0, acc[i][0]);
                acc[i][1] = fmaf(a, b1, acc[i][1]);
                acc[i][2] = fmaf(a, b2, acc[i][2]);
                acc[i][3] = fmaf(a, b3, acc[i][3]);
            }
        }
    }

    // Normalize + merge heads into g_Ctx [B,S,D]
    const int b = bh >> 4;
    const int h = bh & 15;
#pragma unroll
    for (int i = 0; i < 4; i++) {
        const float inv = 1.f / l_i[i];
        const int qi = qb * 64 + ty * 4 + i;
        float4 v = make_float4(acc[i][0] * inv, acc[i][1] * inv,
                               acc[i][2] * inv, acc[i][3] * inv);
        *(float4*)&g_Ctx[((size_t)(b * SEQ + qi)) * DMODEL + h * DK + tx * 4] = v;
    }
}

// ---------------------------------------------------------------------------
extern "C" void kernel_launch(void* const* d_in, const int* in_sizes, int n_in,
                              void* d_out, int out_size) {
    const float* q  = (const float*)d_in[0];
    const float* k  = (const float*)d_in[1];
    const float* v  = (const float*)d_in[2];
    const float* wq = (const float*)d_in[3];
    const float* wk = (const float*)d_in[4];
    const float* wv = (const float*)d_in[5];
    const float* wo = (const float*)d_in[6];
    float* out = (float*)d_out;

    dim3 gg(DMODEL / 128, MROWS / 128);   // (8, 64)
    sgemm_nt<0><<<gg, 256>>>(q, wq, nullptr);
    sgemm_nt<1><<<gg, 256>>>(k, wk, nullptr);
    sgemm_nt<2><<<gg, 256>>>(v, wv, nullptr);

    dim3 ga(SEQ / 64, BATCH * NHEADS);    // (32, 64)
    attn_causal<<<ga, 256>>>();

    sgemm_nt<3><<<gg, 256>>>(nullptr, wo, out);
}

// round 2
// speedup vs baseline: 1.0687x; 1.0687x over previous
#include <cuda_runtime.h>

#define BATCH   4
#define SEQ     2048
#define DMODEL  1024
#define NHEADS  16
#define DK      64
#define MROWS   (BATCH * SEQ)   // 8192

typedef unsigned long long ull;

// Scratch (allocation-free rule: static __device__ arrays).
__device__ float g_Q[BATCH * NHEADS * SEQ * DK];   // [B,H,S,DK]
__device__ float g_K[BATCH * NHEADS * SEQ * DK];
__device__ float g_V[BATCH * NHEADS * SEQ * DK];
__device__ float g_Ctx[BATCH * SEQ * DMODEL];      // merged heads [B,S,D]

// ---- packed f32x2 helpers (Blackwell) -------------------------------------
__device__ __forceinline__ ull pack2(float lo, float hi) {
    ull r;
    asm("mov.b64 %0, {%1, %2};" : "=l"(r) : "f"(lo), "f"(hi));
    return r;
}
__device__ __forceinline__ float2 unpack2(ull v) {
    float2 r;
    asm("mov.b64 {%0, %1}, %2;" : "=f"(r.x), "=f"(r.y) : "l"(v));
    return r;
}
__device__ __forceinline__ void ffma2(ull& acc, ull a, ull b) {
    asm("fma.rn.f32x2 %0, %1, %2, %0;" : "+l"(acc) : "l"(a), "l"(b));
}
__device__ __forceinline__ void fmul2(ull& d, ull a, ull b) {
    asm("mul.rn.f32x2 %0, %1, %2;" : "=l"(d) : "l"(a), "l"(b));
}

// ---------------------------------------------------------------------------
// NT SGEMM via FFMA2: Y[m][n] = sum_k X[m][k] * W[n][k]
// Tile 128x128xBK16, 256 threads, 8x8 per thread (acc paired along n).
// DEST: 0 -> g_Q (head-split), 1 -> g_K, 2 -> g_V, 3 -> Y plain, X := g_Ctx
// ---------------------------------------------------------------------------
template <int DEST>
__global__ void __launch_bounds__(256) sgemm_nt(const float* __restrict__ X,
                                                const float* __restrict__ W,
                                                float* __restrict__ Y) {
    constexpr int K = DMODEL;
    constexpr int N = DMODEL;
    __shared__ float Xs[16][132];   // [k][m], padded
    __shared__ float Ws[16][132];   // [k][n], padded

    const int tid = threadIdx.x;
    const int tx  = tid & 15;
    const int ty  = tid >> 4;
    const int m0  = blockIdx.y * 128;
    const int n0  = blockIdx.x * 128;
    const int lr  = tid >> 2;         // 0..63
    const int lc  = (tid & 3) << 2;   // 0,4,8,12

    const float* Xp = (DEST == 3) ? (const float*)g_Ctx : X;

    ull acc2[8][4];
#pragma unroll
    for (int i = 0; i < 8; i++)
#pragma unroll
        for (int p = 0; p < 4; p++) acc2[i][p] = 0ull;

    const float* xp0 = Xp + (size_t)(m0 + lr) * K + lc;
    const float* xp1 = Xp + (size_t)(m0 + lr + 64) * K + lc;
    const float* wp0 = W + (size_t)(n0 + lr) * K + lc;
    const float* wp1 = W + (size_t)(n0 + lr + 64) * K + lc;

    for (int k0 = 0; k0 < K; k0 += 16) {
        float4 xa = *(const float4*)(xp0 + k0);
        float4 xb = *(const float4*)(xp1 + k0);
        float4 wa = *(const float4*)(wp0 + k0);
        float4 wb = *(const float4*)(wp1 + k0);
        __syncthreads();
        Xs[lc + 0][lr] = xa.x; Xs[lc + 1][lr] = xa.y;
        Xs[lc + 2][lr] = xa.z; Xs[lc + 3][lr] = xa.w;
        Xs[lc + 0][lr + 64] = xb.x; Xs[lc + 1][lr + 64] = xb.y;
        Xs[lc + 2][lr + 64] = xb.z; Xs[lc + 3][lr + 64] = xb.w;
        Ws[lc + 0][lr] = wa.x; Ws[lc + 1][lr] = wa.y;
        Ws[lc + 2][lr] = wa.z; Ws[lc + 3][lr] = wa.w;
        Ws[lc + 0][lr + 64] = wb.x; Ws[lc + 1][lr + 64] = wb.y;
        Ws[lc + 2][lr + 64] = wb.z; Ws[lc + 3][lr + 64] = wb.w;
        __syncthreads();
#pragma unroll
        for (int k = 0; k < 16; k++) {
            float a[8];
            *(float4*)(a + 0) = *(const float4*)&Xs[k][ty * 4];
            *(float4*)(a + 4) = *(const float4*)&Xs[k][64 + ty * 4];
            ull b2[4];
            b2[0] = *(const ull*)&Ws[k][tx * 4];
            b2[1] = *(const ull*)&Ws[k][tx * 4 + 2];
            b2[2] = *(const ull*)&Ws[k][64 + tx * 4];
            b2[3] = *(const ull*)&Ws[k][64 + tx * 4 + 2];
#pragma unroll
            for (int i = 0; i < 8; i++) {
                const ull ad = pack2(a[i], a[i]);
#pragma unroll
                for (int p = 0; p < 4; p++)
                    ffma2(acc2[i][p], ad, b2[p]);
            }
        }
    }

#pragma unroll
    for (int i = 0; i < 8; i++) {
        const int m = m0 + ((i >> 2) << 6) + ty * 4 + (i & 3);
#pragma unroll
        for (int jg = 0; jg < 2; jg++) {
            const int n = n0 + jg * 64 + tx * 4;
            float2 p0 = unpack2(acc2[i][jg * 2 + 0]);
            float2 p1 = unpack2(acc2[i][jg * 2 + 1]);
            float4 v = make_float4(p0.x, p0.y, p1.x, p1.y);
            if (DEST == 3) {
                *(float4*)&Y[(size_t)m * N + n] = v;
            } else {
                float* O = (DEST == 0) ? g_Q : (DEST == 1) ? g_K : g_V;
                const int b  = m >> 11;          // / SEQ
                const int s  = m & (SEQ - 1);
                const int h  = n >> 6;           // / DK
                const int dc = n & (DK - 1);
                *(float4*)&O[((size_t)(b * NHEADS + h) * SEQ + s) * DK + dc] = v;
            }
        }
    }
}

// ---------------------------------------------------------------------------
// Causal flash attention, d_k = 64, FFMA2. Grid: (SEQ/128, B*H). 256 threads.
// Per block: 128 query rows x 64 keys per step. Microtile 8x4 per thread,
// accumulators paired along the row dimension (natural LDS.64 pairs).
// Dyn smem: Qs[64][130] (Q^T), Ks[64][68] (K^T), Vs[64][68], Ps[64][130] (P^T).
// ---------------------------------------------------------------------------
#define QS_STRIDE 130
#define KS_STRIDE 68
#define ATTN_SMEM_FLOATS (64*130 + 64*68 + 64*68 + 64*130)

__global__ void __launch_bounds__(256) attn_causal() {
    extern __shared__ float sm[];
    float* smQ = sm;                         // [64][130]  [d][row]
    float* smK = smQ + 64 * QS_STRIDE;       // [64][68]   [d][j]
    float* smV = smK + 64 * KS_STRIDE;       // [64][68]   [j][d]
    float* smP = smV + 64 * KS_STRIDE;       // [64][130]  [j][row]

    const int tid = threadIdx.x;
    const int tx  = tid & 15;
    const int ty  = tid >> 4;
    const int qb  = gridDim.x - 1 - blockIdx.x;   // heavy blocks first
    const int bh  = blockIdx.y;

    const float* Qg = g_Q + (size_t)bh * SEQ * DK;
    const float* Kg = g_K + (size_t)bh * SEQ * DK;
    const float* Vg = g_V + (size_t)bh * SEQ * DK;

    // Load Q tile transposed: 256 threads, 128 rows, 2 threads/row (32 d each)
    {
        const int row = tid >> 1;
        const int dh  = (tid & 1) * 32;
        const float* q = Qg + (size_t)(qb * 128 + row) * DK + dh;
#pragma unroll
        for (int f = 0; f < 8; f++) {
            float4 v = *(const float4*)(q + f * 4);
            const int d0 = dh + f * 4;
            smQ[(d0 + 0) * QS_STRIDE + row] = v.x;
            smQ[(d0 + 1) * QS_STRIDE + row] = v.y;
            smQ[(d0 + 2) * QS_STRIDE + row] = v.z;
            smQ[(d0 + 3) * QS_STRIDE + row] = v.w;
        }
    }

    ull o2[4][4];
    float m_i[8], l_i[8];
#pragma unroll
    for (int ip = 0; ip < 4; ip++)
#pragma unroll
        for (int j = 0; j < 4; j++) o2[ip][j] = 0ull;
#pragma unroll
    for (int i = 0; i < 8; i++) { m_i[i] = -1e30f; l_i[i] = 0.f; }

    const int kb_end = 2 * qb + 1;
    for (int kb = 0; kb <= kb_end; kb++) {
        __syncthreads();   // previous iter's reads done before overwrite
        if (tid < 128) {   // warps 0-3: K transposed
            const int j  = tid >> 1;
            const int dh = (tid & 1) * 32;
            const float* kp = Kg + (size_t)(kb * 64 + j) * DK + dh;
#pragma unroll
            for (int f = 0; f < 8; f++) {
                float4 v = *(const float4*)(kp + f * 4);
                const int d0 = dh + f * 4;
                smK[(d0 + 0) * KS_STRIDE + j] = v.x;
                smK[(d0 + 1) * KS_STRIDE + j] = v.y;
                smK[(d0 + 2) * KS_STRIDE + j] = v.z;
                smK[(d0 + 3) * KS_STRIDE + j] = v.w;
            }
        } else {           // warps 4-7: V natural
            const int j  = (tid - 128) >> 1;
            const int dh = (tid & 1) * 32;
            const float* vp = Vg + (size_t)(kb * 64 + j) * DK + dh;
#pragma unroll
            for (int f = 0; f < 8; f++)
                *(float4*)&smV[j * KS_STRIDE + dh + f * 4] =
                    *(const float4*)(vp + f * 4);
        }
        __syncthreads();

        // S = Q @ K^T : 8 rows x 4 cols per thread, row-paired FFMA2
        ull qk2[4][4];
#pragma unroll
        for (int ip = 0; ip < 4; ip++)
#pragma unroll
            for (int j = 0; j < 4; j++) qk2[ip][j] = 0ull;

#pragma unroll 8
        for (int d = 0; d < 64; d++) {
            ull a2[4];
#pragma unroll
            for (int ip = 0; ip < 4; ip++)
                a2[ip] = *(const ull*)&smQ[d * QS_STRIDE + ty * 8 + ip * 2];
            float4 bq = *(const float4*)&smK[d * KS_STRIDE + tx * 4];
            ull bd[4];
            bd[0] = pack2(bq.x, bq.x); bd[1] = pack2(bq.y, bq.y);
            bd[2] = pack2(bq.z, bq.z); bd[3] = pack2(bq.w, bq.w);
#pragma unroll
            for (int ip = 0; ip < 4; ip++)
#pragma unroll
                for (int j = 0; j < 4; j++)
                    ffma2(qk2[ip][j], a2[ip], bd[j]);
        }

        float e[8][4];
        const float SC = 0.125f;   // 1/sqrt(64)
#pragma unroll
        for (int ip = 0; ip < 4; ip++)
#pragma unroll
            for (int j = 0; j < 4; j++) {
                float2 p = unpack2(qk2[ip][j]);
                e[2 * ip + 0][j] = p.x * SC;
                e[2 * ip + 1][j] = p.y * SC;
            }

        if (kb >= 2 * qb) {   // diagonal-region blocks: causal mask
            const int rbase = qb * 128 + ty * 8;
            const int cbase = kb * 64 + tx * 4;
#pragma unroll
            for (int i = 0; i < 8; i++)
#pragma unroll
                for (int j = 0; j < 4; j++)
                    if (cbase + j > rbase + i) e[i][j] = -1e9f;
        }

        // Online softmax: row stats across the 16 tx lanes (half-warp)
        float corr[8];
#pragma unroll
        for (int i = 0; i < 8; i++) {
            float rm = fmaxf(fmaxf(e[i][0], e[i][1]), fmaxf(e[i][2], e[i][3]));
#pragma unroll
            for (int o = 8; o; o >>= 1)
                rm = fmaxf(rm, __shfl_xor_sync(0xffffffffu, rm, o));
            const float nm = fmaxf(m_i[i], rm);
            corr[i] = __expf(m_i[i] - nm);
            m_i[i]  = nm;
            float rs = 0.f;
#pragma unroll
            for (int j = 0; j < 4; j++) {
                e[i][j] = __expf(e[i][j] - nm);
                rs += e[i][j];
            }
#pragma unroll
            for (int o = 8; o; o >>= 1)
                rs += __shfl_xor_sync(0xffffffffu, rs, o);
            l_i[i] = l_i[i] * corr[i] + rs;
        }
#pragma unroll
        for (int ip = 0; ip < 4; ip++) {
            const ull c2 = pack2(corr[2 * ip], corr[2 * ip + 1]);
#pragma unroll
            for (int j = 0; j < 4; j++)
                fmul2(o2[ip][j], o2[ip][j], c2);
        }

        // Store P transposed [j][row] as row-pairs
#pragma unroll
        for (int j = 0; j < 4; j++)
#pragma unroll
            for (int ip = 0; ip < 4; ip++)
                *(ull*)&smP[(tx * 4 + j) * QS_STRIDE + ty * 8 + ip * 2] =
                    pack2(e[2 * ip][j], e[2 * ip + 1][j]);
        __syncthreads();

        // acc += P @ V
#pragma unroll 8
        for (int j = 0; j < 64; j++) {
            ull a2[4];
#pragma unroll
            for (int ip = 0; ip < 4; ip++)
                a2[ip] = *(const ull*)&smP[j * QS_STRIDE + ty * 8 + ip * 2];
            float4 bv = *(const float4*)&smV[j * KS_STRIDE + tx * 4];
            ull bd[4];
            bd[0] = pack2(bv.x, bv.x); bd[1] = pack2(bv.y, bv.y);
            bd[2] = pack2(bv.z, bv.z); bd[3] = pack2(bv.w, bv.w);
#pragma unroll
            for (int ip = 0; ip < 4; ip++)
#pragma unroll
                for (int jj = 0; jj < 4; jj++)
                    ffma2(o2[ip][jj], a2[ip], bd[jj]);
        }
    }

    // Normalize + merge heads into g_Ctx [B,S,D]
    const int b = bh >> 4;
    const int h = bh & 15;
    float o[8][4];
#pragma unroll
    for (int ip = 0; ip < 4; ip++)
#pragma unroll
        for (int j = 0; j < 4; j++) {
            float2 p = unpack2(o2[ip][j]);
            o[2 * ip + 0][j] = p.x;
            o[2 * ip + 1][j] = p.y;
        }
#pragma unroll
    for (int i = 0; i < 8; i++) {
        const float inv = 1.f / l_i[i];
        const int qi = qb * 128 + ty * 8 + i;
        float4 v = make_float4(o[i][0] * inv, o[i][1] * inv,
                               o[i][2] * inv, o[i][3] * inv);
        *(float4*)&g_Ctx[((size_t)(b * SEQ + qi)) * DMODEL + h * DK + tx * 4] = v;
    }
}

// ---------------------------------------------------------------------------
extern "C" void kernel_launch(void* const* d_in, const int* in_sizes, int n_in,
                              void* d_out, int out_size) {
    const float* q  = (const float*)d_in[0];
    const float* k  = (const float*)d_in[1];
    const float* v  = (const float*)d_in[2];
    const float* wq = (const float*)d_in[3];
    const float* wk = (const float*)d_in[4];
    const float* wv = (const float*)d_in[5];
    const float* wo = (const float*)d_in[6];
    float* out = (float*)d_out;

    const int attn_smem = ATTN_SMEM_FLOATS * (int)sizeof(float);
    cudaFuncSetAttribute(attn_causal,
                         cudaFuncAttributeMaxDynamicSharedMemorySize, attn_smem);

    dim3 gg(DMODEL / 128, MROWS / 128);   // (8, 64)
    sgemm_nt<0><<<gg, 256>>>(q, wq, nullptr);
    sgemm_nt<1><<<gg, 256>>>(k, wk, nullptr);
    sgemm_nt<2><<<gg, 256>>>(v, wv, nullptr);

    dim3 ga(SEQ / 128, BATCH * NHEADS);   // (16, 64)
    attn_causal<<<ga, 256, attn_smem>>>();

    sgemm_nt<3><<<gg, 256>>>(nullptr, wo, out);
}

// round 4
// speedup vs baseline: 1.5452x; 1.4459x over previous
#include <cuda_runtime.h>
#include <cuda_bf16.h>
#include <cstdint>

#define BATCH   4
#define SEQ     2048
#define DMODEL  1024
#define NHEADS  16
#define DK      64
#define MROWS   (BATCH * SEQ)   // 8192

typedef unsigned long long ull;

// Scratch (allocation-free rule: static __device__ arrays).
__device__ float g_Q[BATCH * NHEADS * SEQ * DK];   // [B,H,S,DK]
__device__ float g_K[BATCH * NHEADS * SEQ * DK];
__device__ float g_V[BATCH * NHEADS * SEQ * DK];
__device__ float g_Ctx[BATCH * SEQ * DMODEL];      // merged heads [B,S,D]

// ============================ helpers ======================================
__device__ __forceinline__ uint32_t smem_u32(const void* p) {
    uint32_t a;
    asm("{ .reg .u64 t; cvta.to.shared.u64 t, %1; cvt.u32.u64 %0, t; }"
        : "=r"(a) : "l"(p));
    return a;
}
#define LDSM_X4(r, addr) \
    asm volatile("ldmatrix.sync.aligned.m8n8.x4.shared.b16 {%0,%1,%2,%3}, [%4];" \
        : "=r"((r)[0]), "=r"((r)[1]), "=r"((r)[2]), "=r"((r)[3]) : "r"(addr))
#define STS128(r0, r1, r2, r3, addr) \
    asm volatile("st.shared.v4.b32 [%0], {%1, %2, %3, %4};" \
                 :: "r"(addr), "r"(r0), "r"(r1), "r"(r2), "r"(r3) : "memory")

__device__ __forceinline__ void mma_bf16(float* c, const uint32_t* a,
                                         uint32_t b0, uint32_t b1) {
    asm volatile("mma.sync.aligned.m16n8k16.row.col.f32.bf16.bf16.f32 "
        "{%0,%1,%2,%3}, {%4,%5,%6,%7}, {%8,%9}, {%0,%1,%2,%3};"
        : "+f"(c[0]), "+f"(c[1]), "+f"(c[2]), "+f"(c[3])
        : "r"(a[0]), "r"(a[1]), "r"(a[2]), "r"(a[3]), "r"(b0), "r"(b1));
}

// fp32 -> bf16 hi + bf16 lo (2-term split), packed as bf16x2 pairs along k.
__device__ __forceinline__ void split_pack2(float x, float y,
                                            uint32_t& hi, uint32_t& lo) {
    __nv_bfloat162 h = __floats2bfloat162_rn(x, y);
    const float rx = x - __bfloat162float(__low2bfloat16(h));
    const float ry = y - __bfloat162float(__high2bfloat16(h));
    __nv_bfloat162 l = __floats2bfloat162_rn(rx, ry);
    hi = *reinterpret_cast<uint32_t*>(&h);
    lo = *reinterpret_cast<uint32_t*>(&l);
}

// ---- packed f32x2 helpers (attention) -------------------------------------
__device__ __forceinline__ ull pack2(float lo, float hi) {
    ull r;
    asm("mov.b64 %0, {%1, %2};" : "=l"(r) : "f"(lo), "f"(hi));
    return r;
}
__device__ __forceinline__ float2 unpack2(ull v) {
    float2 r;
    asm("mov.b64 {%0, %1}, %2;" : "=f"(r.x), "=f"(r.y) : "l"(v));
    return r;
}
__device__ __forceinline__ void ffma2(ull& acc, ull a, ull b) {
    asm("fma.rn.f32x2 %0, %1, %2, %0;" : "+l"(acc) : "l"(a), "l"(b));
}
__device__ __forceinline__ void fmul2(ull& d, ull a, ull b) {
    asm("mul.rn.f32x2 %0, %1, %2;" : "=l"(d) : "l"(a), "l"(b));
}

// ===========================================================================
// HMMA bf16-split NT GEMM: Y[m][n] = sum_k X[m][k] * W[n][k]
// CTA 128x128, BK=32. 8 warps, each 64x32 (warp grid 2m x 4n).
// Split tiles in smem: Ah/Al/Bh/Bl, each [128 rows][32 bf16 data, 40 stride].
// MODE 0: blockIdx.z selects (q,wq)->g_Q, (k,wk)->g_K, (v,wv)->g_V head-split.
// MODE 1: g_Ctx x W -> Y plain.
// ===========================================================================
#define SROW 80            // bytes per smem row (40 bf16), 16B-multiple
#define SA_H 0
#define SA_L 10240
#define SB_H 20480
#define SB_L 30720
#define GEMM_SMEM 40960

template <int MODE>
__global__ void __launch_bounds__(256, 2) gemm_hmma(
    const float* __restrict__ x0, const float* __restrict__ x1,
    const float* __restrict__ x2, const float* __restrict__ w0,
    const float* __restrict__ w1, const float* __restrict__ w2,
    float* __restrict__ Yout) {
    extern __shared__ char smem[];
    const uint32_t sb = smem_u32(smem);

    const int tid  = threadIdx.x;
    const int wid  = tid >> 5;
    const int lane = tid & 31;
    const int m0 = blockIdx.y * 128;
    const int n0 = blockIdx.x * 128;

    const float* X;
    const float* W;
    float* O;
    if (MODE == 0) {
        const int z = blockIdx.z;
        X = (z == 0) ? x0 : (z == 1) ? x1 : x2;
        W = (z == 0) ? w0 : (z == 1) ? w1 : w2;
        O = (z == 0) ? g_Q : (z == 1) ? g_K : g_V;
    } else {
        X = (const float*)g_Ctx;
        W = w0;
        O = Yout;
    }

    // loader mapping: thread -> row (0..127), 16-float half-row
    const int lrow = tid >> 1;
    const int lc0  = (tid & 1) * 16;           // float col within BK=32
    const float* ap = X + (size_t)(m0 + lrow) * DMODEL + lc0;
    const float* bp = W + (size_t)(n0 + lrow) * DMODEL + lc0;
    const uint32_t sAh = sb + SA_H + lrow * SROW + lc0 * 2;
    const uint32_t sAl = sb + SA_L + lrow * SROW + lc0 * 2;
    const uint32_t sBh = sb + SB_H + lrow * SROW + lc0 * 2;
    const uint32_t sBl = sb + SB_L + lrow * SROW + lc0 * 2;

    // mma mapping
    const int wm = (wid & 1) * 64;
    const int wn = (wid >> 1) * 32;
    const int aRow  = lane & 15;
    const int aColB = (lane >> 4) * 16;
    const int bRow  = ((lane >> 4) << 3) + (lane & 7);
    const int bColB = ((lane >> 3) & 1) * 16;
    const uint32_t aFragBase = sb + SA_H + (wm + aRow) * SROW + aColB;
    const uint32_t bFragBase = sb + SB_H + (wn + bRow) * SROW + bColB;

    float acc[4][4][4];
#pragma unroll
    for (int mt = 0; mt < 4; mt++)
#pragma unroll
        for (int nt = 0; nt < 4; nt++)
#pragma unroll
            for (int e = 0; e < 4; e++) acc[mt][nt][e] = 0.f;

    for (int ks = 0; ks < 32; ks++) {
        // ---- load + split + stage ----
        float4 av[4], bv[4];
#pragma unroll
        for (int f = 0; f < 4; f++) {
            av[f] = *(const float4*)(ap + ks * 32 + f * 4);
            bv[f] = *(const float4*)(bp + ks * 32 + f * 4);
        }
        uint32_t ah[8], al[8], bh[8], bl[8];
#pragma unroll
        for (int f = 0; f < 4; f++) {
            split_pack2(av[f].x, av[f].y, ah[f * 2 + 0], al[f * 2 + 0]);
            split_pack2(av[f].z, av[f].w, ah[f * 2 + 1], al[f * 2 + 1]);
            split_pack2(bv[f].x, bv[f].y, bh[f * 2 + 0], bl[f * 2 + 0]);
            split_pack2(bv[f].z, bv[f].w, bh[f * 2 + 1], bl[f * 2 + 1]);
        }
        __syncthreads();   // previous iter's mma reads done
        STS128(ah[0], ah[1], ah[2], ah[3], sAh);
        STS128(ah[4], ah[5], ah[6], ah[7], sAh + 16);
        STS128(al[0], al[1], al[2], al[3], sAl);
        STS128(al[4], al[5], al[6], al[7], sAl + 16);
        STS128(bh[0], bh[1], bh[2], bh[3], sBh);
        STS128(bh[4], bh[5], bh[6], bh[7], sBh + 16);
        STS128(bl[0], bl[1], bl[2], bl[3], sBl);
        STS128(bl[4], bl[5], bl[6], bl[7], sBl + 16);
        __syncthreads();

        // ---- mma: two k16 sub-steps ----
#pragma unroll
        for (int k16 = 0; k16 < 2; k16++) {
            const uint32_t kb = k16 * 32;   // byte offset within row
            uint32_t Af[4][4];
#pragma unroll
            for (int mt = 0; mt < 4; mt++)
                LDSM_X4(Af[mt], aFragBase + mt * (16 * SROW) + kb);
            uint32_t Bh4[2][4], Bl4[2][4];
#pragma unroll
            for (int p = 0; p < 2; p++) {
                LDSM_X4(Bh4[p], bFragBase + p * (16 * SROW) + kb);
                LDSM_X4(Bl4[p], bFragBase + (SB_L - SB_H) + p * (16 * SROW) + kb);
            }
            // ah*bh and ah*bl
#pragma unroll
            for (int mt = 0; mt < 4; mt++)
#pragma unroll
                for (int nt = 0; nt < 4; nt++) {
                    mma_bf16(acc[mt][nt], Af[mt],
                             Bh4[nt >> 1][(nt & 1) * 2], Bh4[nt >> 1][(nt & 1) * 2 + 1]);
                    mma_bf16(acc[mt][nt], Af[mt],
                             Bl4[nt >> 1][(nt & 1) * 2], Bl4[nt >> 1][(nt & 1) * 2 + 1]);
                }
            // al*bh (reuse A fragment registers)
#pragma unroll
            for (int mt = 0; mt < 4; mt++)
                LDSM_X4(Af[mt], aFragBase + (SA_L - SA_H) + mt * (16 * SROW) + kb);
#pragma unroll
            for (int mt = 0; mt < 4; mt++)
#pragma unroll
                for (int nt = 0; nt < 4; nt++)
                    mma_bf16(acc[mt][nt], Af[mt],
                             Bh4[nt >> 1][(nt & 1) * 2], Bh4[nt >> 1][(nt & 1) * 2 + 1]);
        }
    }

    // ---- epilogue ----
    const int g  = lane >> 2;
    const int tq = lane & 3;
#pragma unroll
    for (int mt = 0; mt < 4; mt++) {
#pragma unroll
        for (int nt = 0; nt < 4; nt++) {
            const int mrow = m0 + wm + mt * 16 + g;
            const int ncol = n0 + wn + nt * 8 + tq * 2;
#pragma unroll
            for (int half = 0; half < 2; half++) {
                const int m = mrow + half * 8;
                const float2 v = make_float2(acc[mt][nt][half * 2 + 0],
                                             acc[mt][nt][half * 2 + 1]);
                if (MODE == 1) {
                    *(float2*)&O[(size_t)m * DMODEL + ncol] = v;
                } else {
                    const int b  = m >> 11;
                    const int s  = m & (SEQ - 1);
                    const int h  = ncol >> 6;
                    const int dc = ncol & 63;
                    *(float2*)&O[((size_t)(b * NHEADS + h) * SEQ + s) * DK + dc] = v;
                }
            }
        }
    }
}

// ---------------------------------------------------------------------------
// Causal flash attention, d_k = 64, FFMA2 (unchanged from round 2).
// ---------------------------------------------------------------------------
#define QS_STRIDE 130
#define KS_STRIDE 68
#define ATTN_SMEM_FLOATS (64*130 + 64*68 + 64*68 + 64*130)

__global__ void __launch_bounds__(256) attn_causal() {
    extern __shared__ float sm[];
    float* smQ = sm;                         // [64][130]  [d][row]
    float* smK = smQ + 64 * QS_STRIDE;       // [64][68]   [d][j]
    float* smV = smK + 64 * KS_STRIDE;       // [64][68]   [j][d]
    float* smP = smV + 64 * KS_STRIDE;       // [64][130]  [j][row]

    const int tid = threadIdx.x;
    const int tx  = tid & 15;
    const int ty  = tid >> 4;
    const int qb  = gridDim.x - 1 - blockIdx.x;   // heavy blocks first
    const int bh  = blockIdx.y;

    const float* Qg = g_Q + (size_t)bh * SEQ * DK;
    const float* Kg = g_K + (size_t)bh * SEQ * DK;
    const float* Vg = g_V + (size_t)bh * SEQ * DK;

    {
        const int row = tid >> 1;
        const int dh  = (tid & 1) * 32;
        const float* q = Qg + (size_t)(qb * 128 + row) * DK + dh;
#pragma unroll
        for (int f = 0; f < 8; f++) {
            float4 v = *(const float4*)(q + f * 4);
            const int d0 = dh + f * 4;
            smQ[(d0 + 0) * QS_STRIDE + row] = v.x;
            smQ[(d0 + 1) * QS_STRIDE + row] = v.y;
            smQ[(d0 + 2) * QS_STRIDE + row] = v.z;
            smQ[(d0 + 3) * QS_STRIDE + row] = v.w;
        }
    }

    ull o2[4][4];
    float m_i[8], l_i[8];
#pragma unroll
    for (int ip = 0; ip < 4; ip++)
#pragma unroll
        for (int j = 0; j < 4; j++) o2[ip][j] = 0ull;
#pragma unroll
    for (int i = 0; i < 8; i++) { m_i[i] = -1e30f; l_i[i] = 0.f; }

    const int kb_end = 2 * qb + 1;
    for (int kb = 0; kb <= kb_end; kb++) {
        __syncthreads();
        if (tid < 128) {
            const int j  = tid >> 1;
            const int dh = (tid & 1) * 32;
            const float* kp = Kg + (size_t)(kb * 64 + j) * DK + dh;
#pragma unroll
            for (int f = 0; f < 8; f++) {
                float4 v = *(const float4*)(kp + f * 4);
                const int d0 = dh + f * 4;
                smK[(d0 + 0) * KS_STRIDE + j] = v.x;
                smK[(d0 + 1) * KS_STRIDE + j] = v.y;
                smK[(d0 + 2) * KS_STRIDE + j] = v.z;
                smK[(d0 + 3) * KS_STRIDE + j] = v.w;
            }
        } else {
            const int j  = (tid - 128) >> 1;
            const int dh = (tid & 1) * 32;
            const float* vp = Vg + (size_t)(kb * 64 + j) * DK + dh;
#pragma unroll
            for (int f = 0; f < 8; f++)
                *(float4*)&smV[j * KS_STRIDE + dh + f * 4] =
                    *(const float4*)(vp + f * 4);
        }
        __syncthreads();

        ull qk2[4][4];
#pragma unroll
        for (int ip = 0; ip < 4; ip++)
#pragma unroll
            for (int j = 0; j < 4; j++) qk2[ip][j] = 0ull;

#pragma unroll 8
        for (int d = 0; d < 64; d++) {
            ull a2[4];
#pragma unroll
            for (int ip = 0; ip < 4; ip++)
                a2[ip] = *(const ull*)&smQ[d * QS_STRIDE + ty * 8 + ip * 2];
            float4 bq = *(const float4*)&smK[d * KS_STRIDE + tx * 4];
            ull bd[4];
            bd[0] = pack2(bq.x, bq.x); bd[1] = pack2(bq.y, bq.y);
            bd[2] = pack2(bq.z, bq.z); bd[3] = pack2(bq.w, bq.w);
#pragma unroll
            for (int ip = 0; ip < 4; ip++)
#pragma unroll
                for (int j = 0; j < 4; j++)
                    ffma2(qk2[ip][j], a2[ip], bd[j]);
        }

        float e[8][4];
        const float SC = 0.125f;
#pragma unroll
        for (int ip = 0; ip < 4; ip++)
#pragma unroll
            for (int j = 0; j < 4; j++) {
                float2 p = unpack2(qk2[ip][j]);
                e[2 * ip + 0][j] = p.x * SC;
                e[2 * ip + 1][j] = p.y * SC;
            }

        if (kb >= 2 * qb) {
            const int rbase = qb * 128 + ty * 8;
            const int cbase = kb * 64 + tx * 4;
#pragma unroll
            for (int i = 0; i < 8; i++)
#pragma unroll
                for (int j = 0; j < 4; j++)
                    if (cbase + j > rbase + i) e[i][j] = -1e9f;
        }

        float corr[8];
#pragma unroll
        for (int i = 0; i < 8; i++) {
            float rm = fmaxf(fmaxf(e[i][0], e[i][1]), fmaxf(e[i][2], e[i][3]));
#pragma unroll
            for (int o = 8; o; o >>= 1)
                rm = fmaxf(rm, __shfl_xor_sync(0xffffffffu, rm, o));
            const float nm = fmaxf(m_i[i], rm);
            corr[i] = __expf(m_i[i] - nm);
            m_i[i]  = nm;
            float rs = 0.f;
#pragma unroll
            for (int j = 0; j < 4; j++) {
                e[i][j] = __expf(e[i][j] - nm);
                rs += e[i][j];
            }
#pragma unroll
            for (int o = 8; o; o >>= 1)
                rs += __shfl_xor_sync(0xffffffffu, rs, o);
            l_i[i] = l_i[i] * corr[i] + rs;
        }
#pragma unroll
        for (int ip = 0; ip < 4; ip++) {
            const ull c2 = pack2(corr[2 * ip], corr[2 * ip + 1]);
#pragma unroll
            for (int j = 0; j < 4; j++)
                fmul2(o2[ip][j], o2[ip][j], c2);
        }

#pragma unroll
        for (int j = 0; j < 4; j++)
#pragma unroll
            for (int ip = 0; ip < 4; ip++)
                *(ull*)&smP[(tx * 4 + j) * QS_STRIDE + ty * 8 + ip * 2] =
                    pack2(e[2 * ip][j], e[2 * ip + 1][j]);
        __syncthreads();

#pragma unroll 8
        for (int j = 0; j < 64; j++) {
            ull a2[4];
#pragma unroll
            for (int ip = 0; ip < 4; ip++)
                a2[ip] = *(const ull*)&smP[j * QS_STRIDE + ty * 8 + ip * 2];
            float4 bv = *(const float4*)&smV[j * KS_STRIDE + tx * 4];
            ull bd[4];
            bd[0] = pack2(bv.x, bv.x); bd[1] = pack2(bv.y, bv.y);
            bd[2] = pack2(bv.z, bv.z); bd[3] = pack2(bv.w, bv.w);
#pragma unroll
            for (int ip = 0; ip < 4; ip++)
#pragma unroll
                for (int jj = 0; jj < 4; jj++)
                    ffma2(o2[ip][jj], a2[ip], bd[jj]);
        }
    }

    const int b = bh >> 4;
    const int h = bh & 15;
    float o[8][4];
#pragma unroll
    for (int ip = 0; ip < 4; ip++)
#pragma unroll
        for (int j = 0; j < 4; j++) {
            float2 p = unpack2(o2[ip][j]);
            o[2 * ip + 0][j] = p.x;
            o[2 * ip + 1][j] = p.y;
        }
#pragma unroll
    for (int i = 0; i < 8; i++) {
        const float inv = 1.f / l_i[i];
        const int qi = qb * 128 + ty * 8 + i;
        float4 v = make_float4(o[i][0] * inv, o[i][1] * inv,
                               o[i][2] * inv, o[i][3] * inv);
        *(float4*)&g_Ctx[((size_t)(b * SEQ + qi)) * DMODEL + h * DK + tx * 4] = v;
    }
}

// ---------------------------------------------------------------------------
extern "C" void kernel_launch(void* const* d_in, const int* in_sizes, int n_in,
                              void* d_out, int out_size) {
    const float* q  = (const float*)d_in[0];
    const float* k  = (const float*)d_in[1];
    const float* v  = (const float*)d_in[2];
    const float* wq = (const float*)d_in[3];
    const float* wk = (const float*)d_in[4];
    const float* wv = (const float*)d_in[5];
    const float* wo = (const float*)d_in[6];
    float* out = (float*)d_out;

    static int configured = 0;
    if (!configured) {
        cudaFuncSetAttribute(attn_causal, cudaFuncAttributeMaxDynamicSharedMemorySize,
                             ATTN_SMEM_FLOATS * (int)sizeof(float));
        configured = 1;
    }

    dim3 gqkv(DMODEL / 128, MROWS / 128, 3);   // (8, 64, 3)
    gemm_hmma<0><<<gqkv, 256, GEMM_SMEM>>>(q, k, v, wq, wk, wv, nullptr);

    dim3 ga(SEQ / 128, BATCH * NHEADS);        // (16, 64)
    attn_causal<<<ga, 256, ATTN_SMEM_FLOATS * (int)sizeof(float)>>>();

    dim3 go(DMODEL / 128, MROWS / 128);        // (8, 64)
    gemm_hmma<1><<<go, 256, GEMM_SMEM>>>(nullptr, nullptr, nullptr, wo,
                                         nullptr, nullptr, out);
}

// round 5
// speedup vs baseline: 2.4224x; 1.5677x over previous
#include <cuda_runtime.h>
#include <cuda_bf16.h>
#include <cstdint>

#define BATCH   4
#define SEQ     2048
#define DMODEL  1024
#define NHEADS  16
#define DK      64
#define MROWS   (BATCH * SEQ)   // 8192

typedef unsigned long long ull;

// Scratch (allocation-free rule: static __device__ arrays).
__device__ float g_Q[BATCH * NHEADS * SEQ * DK];   // [B,H,S,DK]
__device__ float g_K[BATCH * NHEADS * SEQ * DK];
__device__ float g_V[BATCH * NHEADS * SEQ * DK];
__device__ float g_Ctx[BATCH * SEQ * DMODEL];      // merged heads [B,S,D]

// ============================ helpers ======================================
__device__ __forceinline__ uint32_t smem_u32(const void* p) {
    uint32_t a;
    asm("{ .reg .u64 t; cvta.to.shared.u64 t, %1; cvt.u32.u64 %0, t; }"
        : "=r"(a) : "l"(p));
    return a;
}
#define LDSM_X4(r, addr) \
    asm volatile("ldmatrix.sync.aligned.m8n8.x4.shared.b16 {%0,%1,%2,%3}, [%4];" \
        : "=r"((r)[0]), "=r"((r)[1]), "=r"((r)[2]), "=r"((r)[3]) : "r"(addr))
#define LDSM_X4_T(r, addr) \
    asm volatile("ldmatrix.sync.aligned.m8n8.x4.trans.shared.b16 {%0,%1,%2,%3}, [%4];" \
        : "=r"((r)[0]), "=r"((r)[1]), "=r"((r)[2]), "=r"((r)[3]) : "r"(addr))
#define STS128(r0, r1, r2, r3, addr) \
    asm volatile("st.shared.v4.b32 [%0], {%1, %2, %3, %4};" \
                 :: "r"(addr), "r"(r0), "r"(r1), "r"(r2), "r"(r3) : "memory")

__device__ __forceinline__ void mma_bf16(float* c, const uint32_t* a,
                                         uint32_t b0, uint32_t b1) {
    asm volatile("mma.sync.aligned.m16n8k16.row.col.f32.bf16.bf16.f32 "
        "{%0,%1,%2,%3}, {%4,%5,%6,%7}, {%8,%9}, {%0,%1,%2,%3};"
        : "+f"(c[0]), "+f"(c[1]), "+f"(c[2]), "+f"(c[3])
        : "r"(a[0]), "r"(a[1]), "r"(a[2]), "r"(a[3]), "r"(b0), "r"(b1));
}

// fp32 -> bf16 hi + bf16 lo (2-term split), packed as bf16x2 pairs along k.
__device__ __forceinline__ void split_pack2(float x, float y,
                                            uint32_t& hi, uint32_t& lo) {
    __nv_bfloat162 h = __floats2bfloat162_rn(x, y);
    const float rx = x - __bfloat162float(__low2bfloat16(h));
    const float ry = y - __bfloat162float(__high2bfloat16(h));
    __nv_bfloat162 l = __floats2bfloat162_rn(rx, ry);
    hi = *reinterpret_cast<uint32_t*>(&h);
    lo = *reinterpret_cast<uint32_t*>(&l);
}

// ===========================================================================
// HMMA bf16-split NT GEMM (unchanged from round 4).
// ===========================================================================
#define SROW 80
#define SA_H 0
#define SA_L 10240
#define SB_H 20480
#define SB_L 30720
#define GEMM_SMEM 40960

template <int MODE>
__global__ void __launch_bounds__(256, 2) gemm_hmma(
    const float* __restrict__ x0, const float* __restrict__ x1,
    const float* __restrict__ x2, const float* __restrict__ w0,
    const float* __restrict__ w1, const float* __restrict__ w2,
    float* __restrict__ Yout) {
    extern __shared__ char smem[];
    const uint32_t sb = smem_u32(smem);

    const int tid  = threadIdx.x;
    const int wid  = tid >> 5;
    const int lane = tid & 31;
    const int m0 = blockIdx.y * 128;
    const int n0 = blockIdx.x * 128;

    const float* X;
    const float* W;
    float* O;
    if (MODE == 0) {
        const int z = blockIdx.z;
        X = (z == 0) ? x0 : (z == 1) ? x1 : x2;
        W = (z == 0) ? w0 : (z == 1) ? w1 : w2;
        O = (z == 0) ? g_Q : (z == 1) ? g_K : g_V;
    } else {
        X = (const float*)g_Ctx;
        W = w0;
        O = Yout;
    }

    const int lrow = tid >> 1;
    const int lc0  = (tid & 1) * 16;
    const float* ap = X + (size_t)(m0 + lrow) * DMODEL + lc0;
    const float* bp = W + (size_t)(n0 + lrow) * DMODEL + lc0;
    const uint32_t sAh = sb + SA_H + lrow * SROW + lc0 * 2;
    const uint32_t sAl = sb + SA_L + lrow * SROW + lc0 * 2;
    const uint32_t sBh = sb + SB_H + lrow * SROW + lc0 * 2;
    const uint32_t sBl = sb + SB_L + lrow * SROW + lc0 * 2;

    const int wm = (wid & 1) * 64;
    const int wn = (wid >> 1) * 32;
    const int aRow  = lane & 15;
    const int aColB = (lane >> 4) * 16;
    const int bRow  = ((lane >> 4) << 3) + (lane & 7);
    const int bColB = ((lane >> 3) & 1) * 16;
    const uint32_t aFragBase = sb + SA_H + (wm + aRow) * SROW + aColB;
    const uint32_t bFragBase = sb + SB_H + (wn + bRow) * SROW + bColB;

    float acc[4][4][4];
#pragma unroll
    for (int mt = 0; mt < 4; mt++)
#pragma unroll
        for (int nt = 0; nt < 4; nt++)
#pragma unroll
            for (int e = 0; e < 4; e++) acc[mt][nt][e] = 0.f;

    for (int ks = 0; ks < 32; ks++) {
        float4 av[4], bv[4];
#pragma unroll
        for (int f = 0; f < 4; f++) {
            av[f] = *(const float4*)(ap + ks * 32 + f * 4);
            bv[f] = *(const float4*)(bp + ks * 32 + f * 4);
        }
        uint32_t ah[8], al[8], bh[8], bl[8];
#pragma unroll
        for (int f = 0; f < 4; f++) {
            split_pack2(av[f].x, av[f].y, ah[f * 2 + 0], al[f * 2 + 0]);
            split_pack2(av[f].z, av[f].w, ah[f * 2 + 1], al[f * 2 + 1]);
            split_pack2(bv[f].x, bv[f].y, bh[f * 2 + 0], bl[f * 2 + 0]);
            split_pack2(bv[f].z, bv[f].w, bh[f * 2 + 1], bl[f * 2 + 1]);
        }
        __syncthreads();
        STS128(ah[0], ah[1], ah[2], ah[3], sAh);
        STS128(ah[4], ah[5], ah[6], ah[7], sAh + 16);
        STS128(al[0], al[1], al[2], al[3], sAl);
        STS128(al[4], al[5], al[6], al[7], sAl + 16);
        STS128(bh[0], bh[1], bh[2], bh[3], sBh);
        STS128(bh[4], bh[5], bh[6], bh[7], sBh + 16);
        STS128(bl[0], bl[1], bl[2], bl[3], sBl);
        STS128(bl[4], bl[5], bl[6], bl[7], sBl + 16);
        __syncthreads();

#pragma unroll
        for (int k16 = 0; k16 < 2; k16++) {
            const uint32_t kb = k16 * 32;
            uint32_t Af[4][4];
#pragma unroll
            for (int mt = 0; mt < 4; mt++)
                LDSM_X4(Af[mt], aFragBase + mt * (16 * SROW) + kb);
            uint32_t Bh4[2][4], Bl4[2][4];
#pragma unroll
            for (int p = 0; p < 2; p++) {
                LDSM_X4(Bh4[p], bFragBase + p * (16 * SROW) + kb);
                LDSM_X4(Bl4[p], bFragBase + (SB_L - SB_H) + p * (16 * SROW) + kb);
            }
#pragma unroll
            for (int mt = 0; mt < 4; mt++)
#pragma unroll
                for (int nt = 0; nt < 4; nt++) {
                    mma_bf16(acc[mt][nt], Af[mt],
                             Bh4[nt >> 1][(nt & 1) * 2], Bh4[nt >> 1][(nt & 1) * 2 + 1]);
                    mma_bf16(acc[mt][nt], Af[mt],
                             Bl4[nt >> 1][(nt & 1) * 2], Bl4[nt >> 1][(nt & 1) * 2 + 1]);
                }
#pragma unroll
            for (int mt = 0; mt < 4; mt++)
                LDSM_X4(Af[mt], aFragBase + (SA_L - SA_H) + mt * (16 * SROW) + kb);
#pragma unroll
            for (int mt = 0; mt < 4; mt++)
#pragma unroll
                for (int nt = 0; nt < 4; nt++)
                    mma_bf16(acc[mt][nt], Af[mt],
                             Bh4[nt >> 1][(nt & 1) * 2], Bh4[nt >> 1][(nt & 1) * 2 + 1]);
        }
    }

    const int g  = lane >> 2;
    const int tq = lane & 3;
#pragma unroll
    for (int mt = 0; mt < 4; mt++) {
#pragma unroll
        for (int nt = 0; nt < 4; nt++) {
            const int mrow = m0 + wm + mt * 16 + g;
            const int ncol = n0 + wn + nt * 8 + tq * 2;
#pragma unroll
            for (int half = 0; half < 2; half++) {
                const int m = mrow + half * 8;
                const float2 v = make_float2(acc[mt][nt][half * 2 + 0],
                                             acc[mt][nt][half * 2 + 1]);
                if (MODE == 1) {
                    *(float2*)&O[(size_t)m * DMODEL + ncol] = v;
                } else {
                    const int b  = m >> 11;
                    const int s  = m & (SEQ - 1);
                    const int h  = ncol >> 6;
                    const int dc = ncol & 63;
                    *(float2*)&O[((size_t)(b * NHEADS + h) * SEQ + s) * DK + dc] = v;
                }
            }
        }
    }
}

// ===========================================================================
// HMMA bf16-split causal flash attention, d_k=64.
// Grid (SEQ/128, B*H), 256 threads, 8 warps x 16 q-rows each, 64 keys/iter.
// Q (scaled, split) lives in registers as mma fragments for the whole block.
// S-accumulator fragments repack in-register into PV A-fragments.
// Smem: Kh/Kl/Vh/Vl [64 rows][72 bf16] (144B stride, conflict-free ldmatrix).
// ===========================================================================
#define BSTR 144
#define ATTN_SMEM (4 * 64 * BSTR)   // 36864

__global__ void __launch_bounds__(256, 1) attn_hmma() {
    extern __shared__ char smem[];
    const uint32_t sb  = smem_u32(smem);
    const uint32_t sKh = sb;
    const uint32_t sKl = sb + 64 * BSTR;
    const uint32_t sVh = sb + 2 * 64 * BSTR;
    const uint32_t sVl = sb + 3 * 64 * BSTR;

    const int tid  = threadIdx.x;
    const int wid  = tid >> 5;
    const int lane = tid & 31;
    const int g    = lane >> 2;
    const int tq   = lane & 3;
    const int qb   = gridDim.x - 1 - blockIdx.x;   // heavy blocks first
    const int bh   = blockIdx.y;

    const float* Qg = g_Q + (size_t)bh * SEQ * DK;
    const float* Kg = g_K + (size_t)bh * SEQ * DK;
    const float* Vg = g_V + (size_t)bh * SEQ * DK;

    // ---- stage Q (scaled by 1/8, split) into smem, then to registers ----
    {
        const int row = tid >> 1;              // 0..127
        const int dc  = (tid & 1) * 32;        // 32 floats per thread
        const float* qp = Qg + (size_t)(qb * 128 + row) * DK + dc;
        uint32_t qh[16], ql[16];
#pragma unroll
        for (int f = 0; f < 8; f++) {
            float4 v = *(const float4*)(qp + f * 4);
            v.x *= 0.125f; v.y *= 0.125f; v.z *= 0.125f; v.w *= 0.125f;
            split_pack2(v.x, v.y, qh[f * 2 + 0], ql[f * 2 + 0]);
            split_pack2(v.z, v.w, qh[f * 2 + 1], ql[f * 2 + 1]);
        }
        // Qh occupies sKh..sKl region (128 rows x 144B), Ql the sVh..sVl region
        const uint32_t ah = sKh + row * BSTR + dc * 2;
        const uint32_t al = sVh + row * BSTR + dc * 2;
#pragma unroll
        for (int f = 0; f < 4; f++) {
            STS128(qh[f*4+0], qh[f*4+1], qh[f*4+2], qh[f*4+3], ah + f * 16);
            STS128(ql[f*4+0], ql[f*4+1], ql[f*4+2], ql[f*4+3], al + f * 16);
        }
    }
    __syncthreads();

    uint32_t Qh[4][4], Ql[4][4];
    {
        const uint32_t qlane = (uint32_t)(wid * 16 + (lane & 15)) * BSTR +
                               (uint32_t)(lane >> 4) * 16;
#pragma unroll
        for (int ks = 0; ks < 4; ks++) {
            LDSM_X4(Qh[ks], sKh + qlane + ks * 32);
            LDSM_X4(Ql[ks], sVh + qlane + ks * 32);
        }
    }

    // ldmatrix lane-offsets for K (non-trans) and V (trans)
    const uint32_t k_lane = (uint32_t)((((lane >> 4) & 1) * 8 + (lane & 7))) * BSTR +
                            (uint32_t)((lane >> 3) & 1) * 16;
    const uint32_t v_lane = (uint32_t)((((lane >> 3) & 1) * 8 + (lane & 7))) * BSTR +
                            (uint32_t)((lane >> 4) & 1) * 16;

    float o[8][4];
#pragma unroll
    for (int nt = 0; nt < 8; nt++)
#pragma unroll
        for (int e = 0; e < 4; e++) o[nt][e] = 0.f;
    float m0 = -1e30f, m1 = -1e30f, l0 = 0.f, l1 = 0.f;

    const int row0 = qb * 128 + wid * 16 + g;      // thread's first q-row
    const int kb_end = 2 * qb + 1;

    for (int kb = 0; kb <= kb_end; kb++) {
        // ---- load K/V tile (fp32), split to bf16 hi/lo, stage ----
        const int krow = tid >> 2;             // 0..63
        const int kdc  = (tid & 3) * 16;       // 16 floats
        const float* kp = Kg + (size_t)(kb * 64 + krow) * DK + kdc;
        const float* vp = Vg + (size_t)(kb * 64 + krow) * DK + kdc;
        uint32_t kh[8], kl[8], vh[8], vl[8];
#pragma unroll
        for (int f = 0; f < 4; f++) {
            float4 a = *(const float4*)(kp + f * 4);
            float4 b = *(const float4*)(vp + f * 4);
            split_pack2(a.x, a.y, kh[f * 2 + 0], kl[f * 2 + 0]);
            split_pack2(a.z, a.w, kh[f * 2 + 1], kl[f * 2 + 1]);
            split_pack2(b.x, b.y, vh[f * 2 + 0], vl[f * 2 + 0]);
            split_pack2(b.z, b.w, vh[f * 2 + 1], vl[f * 2 + 1]);
        }
        __syncthreads();   // previous iteration's ldmatrix reads done
        const uint32_t so = krow * BSTR + kdc * 2;
        STS128(kh[0], kh[1], kh[2], kh[3], sKh + so);
        STS128(kh[4], kh[5], kh[6], kh[7], sKh + so + 16);
        STS128(kl[0], kl[1], kl[2], kl[3], sKl + so);
        STS128(kl[4], kl[5], kl[6], kl[7], sKl + so + 16);
        STS128(vh[0], vh[1], vh[2], vh[3], sVh + so);
        STS128(vh[4], vh[5], vh[6], vh[7], sVh + so + 16);
        STS128(vl[0], vl[1], vl[2], vl[3], sVl + so);
        STS128(vl[4], vl[5], vl[6], vl[7], sVl + so + 16);
        __syncthreads();

        // ---- S = Q K^T (3-product bf16 split) ----
        float s[8][4];
#pragma unroll
        for (int nt = 0; nt < 8; nt++)
#pragma unroll
            for (int e = 0; e < 4; e++) s[nt][e] = 0.f;

#pragma unroll
        for (int ks = 0; ks < 4; ks++) {
#pragma unroll
            for (int np = 0; np < 4; np++) {
                const uint32_t ka = (uint32_t)(np * 16) * BSTR + ks * 32 + k_lane;
                uint32_t KBh[4], KBl[4];
                LDSM_X4(KBh, sKh + ka);
                LDSM_X4(KBl, sKl + ka);
                mma_bf16(s[2*np],   Qh[ks], KBh[0], KBh[1]);
                mma_bf16(s[2*np+1], Qh[ks], KBh[2], KBh[3]);
                mma_bf16(s[2*np],   Qh[ks], KBl[0], KBl[1]);
                mma_bf16(s[2*np+1], Qh[ks], KBl[2], KBl[3]);
                mma_bf16(s[2*np],   Ql[ks], KBh[0], KBh[1]);
                mma_bf16(s[2*np+1], Ql[ks], KBh[2], KBh[3]);
            }
        }

        // ---- causal mask on diagonal-region tiles ----
        if (kb >= 2 * qb) {
            const int cb = kb * 64 + 2 * tq;
#pragma unroll
            for (int nt = 0; nt < 8; nt++) {
                const int c = cb + nt * 8;
                if (c     > row0)     s[nt][0] = -1e9f;
                if (c + 1 > row0)     s[nt][1] = -1e9f;
                if (c     > row0 + 8) s[nt][2] = -1e9f;
                if (c + 1 > row0 + 8) s[nt][3] = -1e9f;
            }
        }

        // ---- online softmax (rows g and g+8; reduce across quad lanes) ----
        float rm0 = -1e30f, rm1 = -1e30f;
#pragma unroll
        for (int nt = 0; nt < 8; nt++) {
            rm0 = fmaxf(rm0, fmaxf(s[nt][0], s[nt][1]));
            rm1 = fmaxf(rm1, fmaxf(s[nt][2], s[nt][3]));
        }
        rm0 = fmaxf(rm0, __shfl_xor_sync(0xffffffffu, rm0, 1));
        rm0 = fmaxf(rm0, __shfl_xor_sync(0xffffffffu, rm0, 2));
        rm1 = fmaxf(rm1, __shfl_xor_sync(0xffffffffu, rm1, 1));
        rm1 = fmaxf(rm1, __shfl_xor_sync(0xffffffffu, rm1, 2));

        const float nm0 = fmaxf(m0, rm0);
        const float nm1 = fmaxf(m1, rm1);
        const float c0 = __expf(m0 - nm0);
        const float c1 = __expf(m1 - nm1);
        m0 = nm0; m1 = nm1;

        float rs0 = 0.f, rs1 = 0.f;
#pragma unroll
        for (int nt = 0; nt < 8; nt++) {
            s[nt][0] = __expf(s[nt][0] - nm0); rs0 += s[nt][0];
            s[nt][1] = __expf(s[nt][1] - nm0); rs0 += s[nt][1];
            s[nt][2] = __expf(s[nt][2] - nm1); rs1 += s[nt][2];
            s[nt][3] = __expf(s[nt][3] - nm1); rs1 += s[nt][3];
        }
        rs0 += __shfl_xor_sync(0xffffffffu, rs0, 1);
        rs0 += __shfl_xor_sync(0xffffffffu, rs0, 2);
        rs1 += __shfl_xor_sync(0xffffffffu, rs1, 1);
        rs1 += __shfl_xor_sync(0xffffffffu, rs1, 2);
        l0 = l0 * c0 + rs0;
        l1 = l1 * c1 + rs1;

#pragma unroll
        for (int nt = 0; nt < 8; nt++) {
            o[nt][0] *= c0; o[nt][1] *= c0;
            o[nt][2] *= c1; o[nt][3] *= c1;
        }

        // ---- O += P V (P repacked in-register, 3-product split) ----
#pragma unroll
        for (int kt = 0; kt < 4; kt++) {
            uint32_t PAh[4], PAl[4];
            split_pack2(s[2*kt][0],   s[2*kt][1],   PAh[0], PAl[0]);
            split_pack2(s[2*kt][2],   s[2*kt][3],   PAh[1], PAl[1]);
            split_pack2(s[2*kt+1][0], s[2*kt+1][1], PAh[2], PAl[2]);
            split_pack2(s[2*kt+1][2], s[2*kt+1][3], PAh[3], PAl[3]);
#pragma unroll
            for (int dp = 0; dp < 4; dp++) {
                const uint32_t va = (uint32_t)(kt * 16) * BSTR + dp * 32 + v_lane;
                uint32_t VBh[4], VBl[4];
                LDSM_X4_T(VBh, sVh + va);
                LDSM_X4_T(VBl, sVl + va);
                mma_bf16(o[2*dp],   PAh, VBh[0], VBh[1]);
                mma_bf16(o[2*dp+1], PAh, VBh[2], VBh[3]);
                mma_bf16(o[2*dp],   PAh, VBl[0], VBl[1]);
                mma_bf16(o[2*dp+1], PAh, VBl[2], VBl[3]);
                mma_bf16(o[2*dp],   PAl, VBh[0], VBh[1]);
                mma_bf16(o[2*dp+1], PAl, VBh[2], VBh[3]);
            }
        }
    }

    // ---- normalize + merge heads into g_Ctx [B,S,D] ----
    const int b = bh >> 4;
    const int h = bh & 15;
    const float i0 = 1.f / l0;
    const float i1 = 1.f / l1;
    float* base0 = &g_Ctx[((size_t)(b * SEQ + row0))     * DMODEL + h * DK + tq * 2];
    float* base1 = &g_Ctx[((size_t)(b * SEQ + row0 + 8)) * DMODEL + h * DK + tq * 2];
#pragma unroll
    for (int nt = 0; nt < 8; nt++) {
        *(float2*)(base0 + nt * 8) = make_float2(o[nt][0] * i0, o[nt][1] * i0);
        *(float2*)(base1 + nt * 8) = make_float2(o[nt][2] * i1, o[nt][3] * i1);
    }
}

// ---------------------------------------------------------------------------
extern "C" void kernel_launch(void* const* d_in, const int* in_sizes, int n_in,
                              void* d_out, int out_size) {
    const float* q  = (const float*)d_in[0];
    const float* k  = (const float*)d_in[1];
    const float* v  = (const float*)d_in[2];
    const float* wq = (const float*)d_in[3];
    const float* wk = (const float*)d_in[4];
    const float* wv = (const float*)d_in[5];
    const float* wo = (const float*)d_in[6];
    float* out = (float*)d_out;

    dim3 gqkv(DMODEL / 128, MROWS / 128, 3);   // (8, 64, 3)
    gemm_hmma<0><<<gqkv, 256, GEMM_SMEM>>>(q, k, v, wq, wk, wv, nullptr);

    dim3 ga(SEQ / 128, BATCH * NHEADS);        // (16, 64)
    attn_hmma<<<ga, 256, ATTN_SMEM>>>();

    dim3 go(DMODEL / 128, MROWS / 128);        // (8, 64)
    gemm_hmma<1><<<go, 256, GEMM_SMEM>>>(nullptr, nullptr, nullptr, wo,
                                         nullptr, nullptr, out);
}

// round 6
// speedup vs baseline: 2.5463x; 1.0512x over previous
#include <cuda_runtime.h>
#include <cuda_bf16.h>
#include <cstdint>

#define BATCH   4
#define SEQ     2048
#define DMODEL  1024
#define NHEADS  16
#define DK      64
#define MROWS   (BATCH * SEQ)                 // 8192
#define HEADELEMS (BATCH * NHEADS * SEQ * DK) // 8M

// ---------------- persistent split scratch (bf16 hi/lo) --------------------
__device__ __nv_bfloat16 g_INh[3 * MROWS * DMODEL];
__device__ __nv_bfloat16 g_INl[3 * MROWS * DMODEL];
__device__ __nv_bfloat16 g_Wh[4 * DMODEL * DMODEL];
__device__ __nv_bfloat16 g_Wl[4 * DMODEL * DMODEL];
__device__ __nv_bfloat16 g_Qh[HEADELEMS], g_Ql[HEADELEMS];
__device__ __nv_bfloat16 g_Kh[HEADELEMS], g_Kl[HEADELEMS];
__device__ __nv_bfloat16 g_Vh[HEADELEMS], g_Vl[HEADELEMS];
__device__ __nv_bfloat16 g_CtxH[MROWS * DMODEL], g_CtxL[MROWS * DMODEL];

// ============================ helpers ======================================
__device__ __forceinline__ uint32_t smem_u32(const void* p) {
    uint32_t a;
    asm("{ .reg .u64 t; cvta.to.shared.u64 t, %1; cvt.u32.u64 %0, t; }"
        : "=r"(a) : "l"(p));
    return a;
}
#define LDSM_X4(r, addr) \
    asm volatile("ldmatrix.sync.aligned.m8n8.x4.shared.b16 {%0,%1,%2,%3}, [%4];" \
        : "=r"((r)[0]), "=r"((r)[1]), "=r"((r)[2]), "=r"((r)[3]) : "r"(addr))
#define LDSM_X4_T(r, addr) \
    asm volatile("ldmatrix.sync.aligned.m8n8.x4.trans.shared.b16 {%0,%1,%2,%3}, [%4];" \
        : "=r"((r)[0]), "=r"((r)[1]), "=r"((r)[2]), "=r"((r)[3]) : "r"(addr))
#define CP16(dst, src) \
    asm volatile("cp.async.cg.shared.global [%0], [%1], 16;" \
                 :: "r"(dst), "l"(src) : "memory")
#define CP_COMMIT() asm volatile("cp.async.commit_group;" ::: "memory")
#define CP_WAIT0()  asm volatile("cp.async.wait_group 0;" ::: "memory")

__device__ __forceinline__ void mma_bf16(float* c, const uint32_t* a,
                                         uint32_t b0, uint32_t b1) {
    asm volatile("mma.sync.aligned.m16n8k16.row.col.f32.bf16.bf16.f32 "
        "{%0,%1,%2,%3}, {%4,%5,%6,%7}, {%8,%9}, {%0,%1,%2,%3};"
        : "+f"(c[0]), "+f"(c[1]), "+f"(c[2]), "+f"(c[3])
        : "r"(a[0]), "r"(a[1]), "r"(a[2]), "r"(a[3]), "r"(b0), "r"(b1));
}

__device__ __forceinline__ void split_pack2(float x, float y,
                                            uint32_t& hi, uint32_t& lo) {
    __nv_bfloat162 h = __floats2bfloat162_rn(x, y);
    const float rx = x - __bfloat162float(__low2bfloat16(h));
    const float ry = y - __bfloat162float(__high2bfloat16(h));
    __nv_bfloat162 l = __floats2bfloat162_rn(rx, ry);
    hi = *reinterpret_cast<uint32_t*>(&h);
    lo = *reinterpret_cast<uint32_t*>(&l);
}

// ===========================================================================
// Pre-split pass: fp32 -> bf16 hi/lo. grid (4096, 7): y 0-2 inputs, 3-6 weights
// ===========================================================================
__global__ void __launch_bounds__(256) ksplit(
    const float* __restrict__ q, const float* __restrict__ k,
    const float* __restrict__ v, const float* __restrict__ wq,
    const float* __restrict__ wk, const float* __restrict__ wv,
    const float* __restrict__ wo) {
    const int sel = blockIdx.y;
    const float* src;
    __nv_bfloat16 *h, *l;
    int n;
    if (sel < 3) {
        src = (sel == 0) ? q : (sel == 1) ? k : v;
        h = g_INh + (size_t)sel * MROWS * DMODEL;
        l = g_INl + (size_t)sel * MROWS * DMODEL;
        n = MROWS * DMODEL;
    } else {
        const int w = sel - 3;
        src = (w == 0) ? wq : (w == 1) ? wk : (w == 2) ? wv : wo;
        h = g_Wh + (size_t)w * DMODEL * DMODEL;
        l = g_Wl + (size_t)w * DMODEL * DMODEL;
        n = DMODEL * DMODEL;
    }
    const int i = (blockIdx.x * 256 + threadIdx.x) * 8;
    if (i >= n) return;
    const float4 a = *(const float4*)(src + i);
    const float4 b = *(const float4*)(src + i + 4);
    uint32_t h0, l0, h1, l1, h2, l2, h3, l3;
    split_pack2(a.x, a.y, h0, l0);
    split_pack2(a.z, a.w, h1, l1);
    split_pack2(b.x, b.y, h2, l2);
    split_pack2(b.z, b.w, h3, l3);
    *(uint4*)(h + i) = make_uint4(h0, h1, h2, h3);
    *(uint4*)(l + i) = make_uint4(l0, l1, l2, l3);
}

// ===========================================================================
// bf16-split HMMA NT GEMM, cp.async double-buffered. CTA 128x128, BK=32.
// MODE 0: z -> (input z, weight z) -> split Q/K/V head-split bf16.
// MODE 1: Ctx split x Wo -> Y fp32.
// ===========================================================================
#define GS_ROW   80
#define GS_TILE  10240          // 128 * 80
#define GS_STAGE 40960          // 4 tiles
#define GEMM_SMEM (2 * GS_STAGE)

template <int MODE>
__global__ void __launch_bounds__(256, 2) gemm_hmma(float* __restrict__ Yout) {
    extern __shared__ char smem[];
    const uint32_t sb = smem_u32(smem);
    const int tid  = threadIdx.x;
    const int wid  = tid >> 5;
    const int lane = tid & 31;
    const int m0 = blockIdx.y * 128;
    const int n0 = blockIdx.x * 128;

    const __nv_bfloat16 *Ah, *Al, *Bh, *Bl;
    int z = 0;
    if (MODE == 0) {
        z  = blockIdx.z;
        Ah = g_INh + (size_t)z * MROWS * DMODEL;
        Al = g_INl + (size_t)z * MROWS * DMODEL;
        Bh = g_Wh + (size_t)z * DMODEL * DMODEL;
        Bl = g_Wl + (size_t)z * DMODEL * DMODEL;
    } else {
        Ah = g_CtxH; Al = g_CtxL;
        Bh = g_Wh + (size_t)3 * DMODEL * DMODEL;
        Bl = g_Wl + (size_t)3 * DMODEL * DMODEL;
    }

    // prefetch mapping: 2 threads per row, 2 16B chunks each (row = 32 bf16 = 64B)
    const int prow = tid >> 1;
    const int pc   = (tid & 1) * 2;
    const __nv_bfloat16* srcAh = Ah + (size_t)(m0 + prow) * DMODEL + pc * 8;
    const __nv_bfloat16* srcAl = Al + (size_t)(m0 + prow) * DMODEL + pc * 8;
    const __nv_bfloat16* srcBh = Bh + (size_t)(n0 + prow) * DMODEL + pc * 8;
    const __nv_bfloat16* srcBl = Bl + (size_t)(n0 + prow) * DMODEL + pc * 8;
    const uint32_t pdst = (uint32_t)prow * GS_ROW + pc * 16;

    auto prefetch = [&](int ks, int st) {
        const uint32_t s0 = sb + st * GS_STAGE + pdst;
        const int ko = ks * 32;
        CP16(s0 + 0 * GS_TILE,      srcAh + ko);
        CP16(s0 + 0 * GS_TILE + 16, srcAh + ko + 8);
        CP16(s0 + 1 * GS_TILE,      srcAl + ko);
        CP16(s0 + 1 * GS_TILE + 16, srcAl + ko + 8);
        CP16(s0 + 2 * GS_TILE,      srcBh + ko);
        CP16(s0 + 2 * GS_TILE + 16, srcBh + ko + 8);
        CP16(s0 + 3 * GS_TILE,      srcBl + ko);
        CP16(s0 + 3 * GS_TILE + 16, srcBl + ko + 8);
    };

    // mma fragment mapping
    const int wm = (wid & 1) * 64;
    const int wn = (wid >> 1) * 32;
    const int aRow  = lane & 15;
    const int aColB = (lane >> 4) * 16;
    const int bRow  = ((lane >> 4) << 3) + (lane & 7);
    const int bColB = ((lane >> 3) & 1) * 16;
    const uint32_t aOff = (uint32_t)(wm + aRow) * GS_ROW + aColB;
    const uint32_t bOff = (uint32_t)(wn + bRow) * GS_ROW + bColB;

    float acc[4][4][4];
#pragma unroll
    for (int mt = 0; mt < 4; mt++)
#pragma unroll
        for (int nt = 0; nt < 4; nt++)
#pragma unroll
            for (int e = 0; e < 4; e++) acc[mt][nt][e] = 0.f;

    prefetch(0, 0);
    CP_COMMIT();

    for (int ks = 0; ks < 32; ks++) {
        CP_WAIT0();
        __syncthreads();
        if (ks < 31) {
            prefetch(ks + 1, (ks + 1) & 1);
            CP_COMMIT();
        }
        const uint32_t st = sb + (ks & 1) * GS_STAGE;
        const uint32_t aH = st + aOff;
        const uint32_t aL = st + GS_TILE + aOff;
        const uint32_t bH = st + 2 * GS_TILE + bOff;
        const uint32_t bL = st + 3 * GS_TILE + bOff;

#pragma unroll
        for (int k16 = 0; k16 < 2; k16++) {
            const uint32_t kb = k16 * 32;
            uint32_t Af[4][4];
#pragma unroll
            for (int mt = 0; mt < 4; mt++)
                LDSM_X4(Af[mt], aH + mt * (16 * GS_ROW) + kb);
            uint32_t Bh4[2][4], Bl4[2][4];
#pragma unroll
            for (int p = 0; p < 2; p++) {
                LDSM_X4(Bh4[p], bH + p * (16 * GS_ROW) + kb);
                LDSM_X4(Bl4[p], bL + p * (16 * GS_ROW) + kb);
            }
#pragma unroll
            for (int mt = 0; mt < 4; mt++)
#pragma unroll
                for (int nt = 0; nt < 4; nt++) {
                    mma_bf16(acc[mt][nt], Af[mt],
                             Bh4[nt >> 1][(nt & 1) * 2], Bh4[nt >> 1][(nt & 1) * 2 + 1]);
                    mma_bf16(acc[mt][nt], Af[mt],
                             Bl4[nt >> 1][(nt & 1) * 2], Bl4[nt >> 1][(nt & 1) * 2 + 1]);
                }
#pragma unroll
            for (int mt = 0; mt < 4; mt++)
                LDSM_X4(Af[mt], aL + mt * (16 * GS_ROW) + kb);
#pragma unroll
            for (int mt = 0; mt < 4; mt++)
#pragma unroll
                for (int nt = 0; nt < 4; nt++)
                    mma_bf16(acc[mt][nt], Af[mt],
                             Bh4[nt >> 1][(nt & 1) * 2], Bh4[nt >> 1][(nt & 1) * 2 + 1]);
        }
        __syncthreads();
    }

    // ---- epilogue ----
    __nv_bfloat16 *OH = nullptr, *OL = nullptr;
    if (MODE == 0) {
        OH = (z == 0) ? g_Qh : (z == 1) ? g_Kh : g_Vh;
        OL = (z == 0) ? g_Ql : (z == 1) ? g_Kl : g_Vl;
    }
    const int g  = lane >> 2;
    const int tq = lane & 3;
#pragma unroll
    for (int mt = 0; mt < 4; mt++) {
#pragma unroll
        for (int nt = 0; nt < 4; nt++) {
            const int mrow = m0 + wm + mt * 16 + g;
            const int ncol = n0 + wn + nt * 8 + tq * 2;
#pragma unroll
            for (int half = 0; half < 2; half++) {
                const int m = mrow + half * 8;
                const float v0 = acc[mt][nt][half * 2 + 0];
                const float v1 = acc[mt][nt][half * 2 + 1];
                if (MODE == 1) {
                    *(float2*)&Yout[(size_t)m * DMODEL + ncol] = make_float2(v0, v1);
                } else {
                    const int b  = m >> 11;
                    const int s  = m & (SEQ - 1);
                    const int h  = ncol >> 6;
                    const int dc = ncol & 63;
                    const size_t off = ((size_t)(b * NHEADS + h) * SEQ + s) * DK + dc;
                    uint32_t hi, lo;
                    split_pack2(v0, v1, hi, lo);
                    *(uint32_t*)&OH[off] = hi;
                    *(uint32_t*)&OL[off] = lo;
                }
            }
        }
    }
}

// ===========================================================================
// HMMA bf16-split causal flash attention, pre-split inputs, cp.async pipeline.
// Grid (SEQ/128, B*H), 256 threads, 8 warps x 16 q-rows, 64 keys/iter.
// ===========================================================================
#define BSTR     144
#define KV_TILE  (64 * BSTR)      // 9216
#define KV_STAGE (4 * KV_TILE)    // 36864
#define ATTN_SMEM (2 * KV_STAGE)  // 73728

__global__ void __launch_bounds__(256) attn_hmma() {
    extern __shared__ char smem[];
    const uint32_t sb = smem_u32(smem);

    const int tid  = threadIdx.x;
    const int wid  = tid >> 5;
    const int lane = tid & 31;
    const int g    = lane >> 2;
    const int tq   = lane & 3;
    const int qb   = gridDim.x - 1 - blockIdx.x;   // heavy blocks first
    const int bh   = blockIdx.y;

    const size_t hbase = (size_t)bh * SEQ * DK;

    // ---- stage Q hi/lo via cp.async, load fragments ----
    {
        const int row = tid >> 1;
        const int c0  = (tid & 1) * 4;    // 4 chunks of 16B each
        const __nv_bfloat16* qh = g_Qh + hbase + (size_t)(qb * 128 + row) * DK + c0 * 8;
        const __nv_bfloat16* ql = g_Ql + hbase + (size_t)(qb * 128 + row) * DK + c0 * 8;
        const uint32_t dh = sb + (uint32_t)row * BSTR + c0 * 16;
        const uint32_t dl = dh + 128 * BSTR;
#pragma unroll
        for (int c = 0; c < 4; c++) {
            CP16(dh + c * 16, qh + c * 8);
            CP16(dl + c * 16, ql + c * 8);
        }
        CP_COMMIT();
    }
    CP_WAIT0();
    __syncthreads();

    uint32_t Qh[4][4], Ql[4][4];
    {
        const uint32_t qlane = (uint32_t)(wid * 16 + (lane & 15)) * BSTR +
                               (uint32_t)(lane >> 4) * 16;
#pragma unroll
        for (int ks = 0; ks < 4; ks++) {
            LDSM_X4(Qh[ks], sb + qlane + ks * 32);
            LDSM_X4(Ql[ks], sb + 128 * BSTR + qlane + ks * 32);
        }
    }
    __syncthreads();

    // KV prefetch mapping: 4 threads per row, 2 chunks each
    const int krow = tid >> 2;
    const int kc0  = (tid & 3) * 2;
    const __nv_bfloat16* sKh = g_Kh + hbase + (size_t)krow * DK + kc0 * 8;
    const __nv_bfloat16* sKl = g_Kl + hbase + (size_t)krow * DK + kc0 * 8;
    const __nv_bfloat16* sVh = g_Vh + hbase + (size_t)krow * DK + kc0 * 8;
    const __nv_bfloat16* sVl = g_Vl + hbase + (size_t)krow * DK + kc0 * 8;
    const uint32_t kdst = (uint32_t)krow * BSTR + kc0 * 16;

    auto prefetchKV = [&](int kb, int st) {
        const uint32_t s0 = sb + st * KV_STAGE + kdst;
        const size_t ko = (size_t)kb * 64 * DK;
#pragma unroll
        for (int c = 0; c < 2; c++) {
            CP16(s0 + 0 * KV_TILE + c * 16, sKh + ko + c * 8);
            CP16(s0 + 1 * KV_TILE + c * 16, sKl + ko + c * 8);
            CP16(s0 + 2 * KV_TILE + c * 16, sVh + ko + c * 8);
            CP16(s0 + 3 * KV_TILE + c * 16, sVl + ko + c * 8);
        }
    };

    const uint32_t k_lane = (uint32_t)((((lane >> 4) & 1) * 8 + (lane & 7))) * BSTR +
                            (uint32_t)((lane >> 3) & 1) * 16;
    const uint32_t v_lane = (uint32_t)((((lane >> 3) & 1) * 8 + (lane & 7))) * BSTR +
                            (uint32_t)((lane >> 4) & 1) * 16;

    float o[8][4];
#pragma unroll
    for (int nt = 0; nt < 8; nt++)
#pragma unroll
        for (int e = 0; e < 4; e++) o[nt][e] = 0.f;
    float m0 = -1e30f, m1 = -1e30f, l0 = 0.f, l1 = 0.f;

    const int row0 = qb * 128 + wid * 16 + g;
    const int kb_end = 2 * qb + 1;

    prefetchKV(0, 0);
    CP_COMMIT();

    for (int kb = 0; kb <= kb_end; kb++) {
        CP_WAIT0();
        __syncthreads();
        if (kb < kb_end) {
            prefetchKV(kb + 1, (kb + 1) & 1);
            CP_COMMIT();
        }
        const uint32_t st = sb + (kb & 1) * KV_STAGE;

        // ---- S = Q K^T (3-product split) ----
        float s[8][4];
#pragma unroll
        for (int nt = 0; nt < 8; nt++)
#pragma unroll
            for (int e = 0; e < 4; e++) s[nt][e] = 0.f;

#pragma unroll
        for (int ks = 0; ks < 4; ks++) {
#pragma unroll
            for (int np = 0; np < 4; np++) {
                const uint32_t ka = (uint32_t)(np * 16) * BSTR + ks * 32 + k_lane;
                uint32_t KBh[4], KBl[4];
                LDSM_X4(KBh, st + ka);
                LDSM_X4(KBl, st + KV_TILE + ka);
                mma_bf16(s[2*np],   Qh[ks], KBh[0], KBh[1]);
                mma_bf16(s[2*np+1], Qh[ks], KBh[2], KBh[3]);
                mma_bf16(s[2*np],   Qh[ks], KBl[0], KBl[1]);
                mma_bf16(s[2*np+1], Qh[ks], KBl[2], KBl[3]);
                mma_bf16(s[2*np],   Ql[ks], KBh[0], KBh[1]);
                mma_bf16(s[2*np+1], Ql[ks], KBh[2], KBh[3]);
            }
        }

        // ---- scale + causal mask ----
#pragma unroll
        for (int nt = 0; nt < 8; nt++)
#pragma unroll
            for (int e = 0; e < 4; e++) s[nt][e] *= 0.125f;

        if (kb >= 2 * qb) {
            const int cb = kb * 64 + 2 * tq;
#pragma unroll
            for (int nt = 0; nt < 8; nt++) {
                const int c = cb + nt * 8;
                if (c     > row0)     s[nt][0] = -1e9f;
                if (c + 1 > row0)     s[nt][1] = -1e9f;
                if (c     > row0 + 8) s[nt][2] = -1e9f;
                if (c + 1 > row0 + 8) s[nt][3] = -1e9f;
            }
        }

        // ---- online softmax ----
        float rm0 = -1e30f, rm1 = -1e30f;
#pragma unroll
        for (int nt = 0; nt < 8; nt++) {
            rm0 = fmaxf(rm0, fmaxf(s[nt][0], s[nt][1]));
            rm1 = fmaxf(rm1, fmaxf(s[nt][2], s[nt][3]));
        }
        rm0 = fmaxf(rm0, __shfl_xor_sync(0xffffffffu, rm0, 1));
        rm0 = fmaxf(rm0, __shfl_xor_sync(0xffffffffu, rm0, 2));
        rm1 = fmaxf(rm1, __shfl_xor_sync(0xffffffffu, rm1, 1));
        rm1 = fmaxf(rm1, __shfl_xor_sync(0xffffffffu, rm1, 2));

        const float nm0 = fmaxf(m0, rm0);
        const float nm1 = fmaxf(m1, rm1);
        const float c0 = __expf(m0 - nm0);
        const float c1 = __expf(m1 - nm1);
        m0 = nm0; m1 = nm1;

        float rs0 = 0.f, rs1 = 0.f;
#pragma unroll
        for (int nt = 0; nt < 8; nt++) {
            s[nt][0] = __expf(s[nt][0] - nm0); rs0 += s[nt][0];
            s[nt][1] = __expf(s[nt][1] - nm0); rs0 += s[nt][1];
            s[nt][2] = __expf(s[nt][2] - nm1); rs1 += s[nt][2];
            s[nt][3] = __expf(s[nt][3] - nm1); rs1 += s[nt][3];
        }
        rs0 += __shfl_xor_sync(0xffffffffu, rs0, 1);
        rs0 += __shfl_xor_sync(0xffffffffu, rs0, 2);
        rs1 += __shfl_xor_sync(0xffffffffu, rs1, 1);
        rs1 += __shfl_xor_sync(0xffffffffu, rs1, 2);
        l0 = l0 * c0 + rs0;
        l1 = l1 * c1 + rs1;

#pragma unroll
        for (int nt = 0; nt < 8; nt++) {
            o[nt][0] *= c0; o[nt][1] *= c0;
            o[nt][2] *= c1; o[nt][3] *= c1;
        }

        // ---- O += P V (in-register split) ----
#pragma unroll
        for (int kt = 0; kt < 4; kt++) {
            uint32_t PAh[4], PAl[4];
            split_pack2(s[2*kt][0],   s[2*kt][1],   PAh[0], PAl[0]);
            split_pack2(s[2*kt][2],   s[2*kt][3],   PAh[1], PAl[1]);
            split_pack2(s[2*kt+1][0], s[2*kt+1][1], PAh[2], PAl[2]);
            split_pack2(s[2*kt+1][2], s[2*kt+1][3], PAh[3], PAl[3]);
#pragma unroll
            for (int dp = 0; dp < 4; dp++) {
                const uint32_t va = (uint32_t)(kt * 16) * BSTR + dp * 32 + v_lane;
                uint32_t VBh[4], VBl[4];
                LDSM_X4_T(VBh, st + 2 * KV_TILE + va);
                LDSM_X4_T(VBl, st + 3 * KV_TILE + va);
                mma_bf16(o[2*dp],   PAh, VBh[0], VBh[1]);
                mma_bf16(o[2*dp+1], PAh, VBh[2], VBh[3]);
                mma_bf16(o[2*dp],   PAh, VBl[0], VBl[1]);
                mma_bf16(o[2*dp+1], PAh, VBl[2], VBl[3]);
                mma_bf16(o[2*dp],   PAl, VBh[0], VBh[1]);
                mma_bf16(o[2*dp+1], PAl, VBh[2], VBh[3]);
            }
        }
        __syncthreads();
    }

    // ---- normalize + split-store merged heads ----
    const int b = bh >> 4;
    const int h = bh & 15;
    const float i0 = 1.f / l0;
    const float i1 = 1.f / l1;
    const size_t off0 = ((size_t)(b * SEQ + row0))     * DMODEL + h * DK + tq * 2;
    const size_t off1 = ((size_t)(b * SEQ + row0 + 8)) * DMODEL + h * DK + tq * 2;
#pragma unroll
    for (int nt = 0; nt < 8; nt++) {
        uint32_t hi, lo;
        split_pack2(o[nt][0] * i0, o[nt][1] * i0, hi, lo);
        *(uint32_t*)&g_CtxH[off0 + nt * 8] = hi;
        *(uint32_t*)&g_CtxL[off0 + nt * 8] = lo;
        split_pack2(o[nt][2] * i1, o[nt][3] * i1, hi, lo);
        *(uint32_t*)&g_CtxH[off1 + nt * 8] = hi;
        *(uint32_t*)&g_CtxL[off1 + nt * 8] = lo;
    }
}

// ---------------------------------------------------------------------------
extern "C" void kernel_launch(void* const* d_in, const int* in_sizes, int n_in,
                              void* d_out, int out_size) {
    const float* q  = (const float*)d_in[0];
    const float* k  = (const float*)d_in[1];
    const float* v  = (const float*)d_in[2];
    const float* wq = (const float*)d_in[3];
    const float* wk = (const float*)d_in[4];
    const float* wv = (const float*)d_in[5];
    const float* wo = (const float*)d_in[6];
    float* out = (float*)d_out;

    static int configured = 0;
    if (!configured) {
        cudaFuncSetAttribute(gemm_hmma<0>, cudaFuncAttributeMaxDynamicSharedMemorySize, GEMM_SMEM);
        cudaFuncSetAttribute(gemm_hmma<1>, cudaFuncAttributeMaxDynamicSharedMemorySize, GEMM_SMEM);
        cudaFuncSetAttribute(attn_hmma, cudaFuncAttributeMaxDynamicSharedMemorySize, ATTN_SMEM);
        configured = 1;
    }

    dim3 gs(MROWS * DMODEL / (256 * 8), 7);    // (4096, 7)
    ksplit<<<gs, 256>>>(q, k, v, wq, wk, wv, wo);

    dim3 gqkv(DMODEL / 128, MROWS / 128, 3);   // (8, 64, 3)
    gemm_hmma<0><<<gqkv, 256, GEMM_SMEM>>>(nullptr);

    dim3 ga(SEQ / 128, BATCH * NHEADS);        // (16, 64)
    attn_hmma<<<ga, 256, ATTN_SMEM>>>();

    dim3 go(DMODEL / 128, MROWS / 128);        // (8, 64)
    gemm_hmma<1><<<go, 256, GEMM_SMEM>>>(out);
}

// round 7
// speedup vs baseline: 2.5934x; 1.0185x over previous
#include <cuda_runtime.h>
#include <cuda_bf16.h>
#include <cstdint>

#define BATCH   4
#define SEQ     2048
#define DMODEL  1024
#define NHEADS  16
#define DK      64
#define MROWS   (BATCH * SEQ)                 // 8192
#define HEADELEMS (BATCH * NHEADS * SEQ * DK) // 8M

// ---------------- persistent split scratch (bf16 hi/lo) --------------------
__device__ __nv_bfloat16 g_INh[3 * MROWS * DMODEL];
__device__ __nv_bfloat16 g_INl[3 * MROWS * DMODEL];
__device__ __nv_bfloat16 g_Wh[4 * DMODEL * DMODEL];
__device__ __nv_bfloat16 g_Wl[4 * DMODEL * DMODEL];
__device__ __nv_bfloat16 g_Qh[HEADELEMS], g_Ql[HEADELEMS];
__device__ __nv_bfloat16 g_Kh[HEADELEMS], g_Kl[HEADELEMS];
__device__ __nv_bfloat16 g_Vh[HEADELEMS], g_Vl[HEADELEMS];
__device__ __nv_bfloat16 g_CtxH[MROWS * DMODEL], g_CtxL[MROWS * DMODEL];

// ============================ helpers ======================================
__device__ __forceinline__ uint32_t smem_u32(const void* p) {
    uint32_t a;
    asm("{ .reg .u64 t; cvta.to.shared.u64 t, %1; cvt.u32.u64 %0, t; }"
        : "=r"(a) : "l"(p));
    return a;
}
#define LDSM_X4(r, addr) \
    asm volatile("ldmatrix.sync.aligned.m8n8.x4.shared.b16 {%0,%1,%2,%3}, [%4];" \
        : "=r"((r)[0]), "=r"((r)[1]), "=r"((r)[2]), "=r"((r)[3]) : "r"(addr))
#define LDSM_X4_T(r, addr) \
    asm volatile("ldmatrix.sync.aligned.m8n8.x4.trans.shared.b16 {%0,%1,%2,%3}, [%4];" \
        : "=r"((r)[0]), "=r"((r)[1]), "=r"((r)[2]), "=r"((r)[3]) : "r"(addr))
#define CP16(dst, src) \
    asm volatile("cp.async.cg.shared.global [%0], [%1], 16;" \
                 :: "r"(dst), "l"(src) : "memory")
#define CP_COMMIT() asm volatile("cp.async.commit_group;" ::: "memory")
#define CP_WAIT0()  asm volatile("cp.async.wait_group 0;" ::: "memory")

__device__ __forceinline__ void mma_bf16(float* c, const uint32_t* a,
                                         uint32_t b0, uint32_t b1) {
    asm volatile("mma.sync.aligned.m16n8k16.row.col.f32.bf16.bf16.f32 "
        "{%0,%1,%2,%3}, {%4,%5,%6,%7}, {%8,%9}, {%0,%1,%2,%3};"
        : "+f"(c[0]), "+f"(c[1]), "+f"(c[2]), "+f"(c[3])
        : "r"(a[0]), "r"(a[1]), "r"(a[2]), "r"(a[3]), "r"(b0), "r"(b1));
}

__device__ __forceinline__ void split_pack2(float x, float y,
                                            uint32_t& hi, uint32_t& lo) {
    __nv_bfloat162 h = __floats2bfloat162_rn(x, y);
    const float rx = x - __bfloat162float(__low2bfloat16(h));
    const float ry = y - __bfloat162float(__high2bfloat16(h));
    __nv_bfloat162 l = __floats2bfloat162_rn(rx, ry);
    hi = *reinterpret_cast<uint32_t*>(&h);
    lo = *reinterpret_cast<uint32_t*>(&l);
}

// ===========================================================================
// Pre-split pass (unchanged).
// ===========================================================================
__global__ void __launch_bounds__(256) ksplit(
    const float* __restrict__ q, const float* __restrict__ k,
    const float* __restrict__ v, const float* __restrict__ wq,
    const float* __restrict__ wk, const float* __restrict__ wv,
    const float* __restrict__ wo) {
    const int sel = blockIdx.y;
    const float* src;
    __nv_bfloat16 *h, *l;
    int n;
    if (sel < 3) {
        src = (sel == 0) ? q : (sel == 1) ? k : v;
        h = g_INh + (size_t)sel * MROWS * DMODEL;
        l = g_INl + (size_t)sel * MROWS * DMODEL;
        n = MROWS * DMODEL;
    } else {
        const int w = sel - 3;
        src = (w == 0) ? wq : (w == 1) ? wk : (w == 2) ? wv : wo;
        h = g_Wh + (size_t)w * DMODEL * DMODEL;
        l = g_Wl + (size_t)w * DMODEL * DMODEL;
        n = DMODEL * DMODEL;
    }
    const int i = (blockIdx.x * 256 + threadIdx.x) * 8;
    if (i >= n) return;
    const float4 a = *(const float4*)(src + i);
    const float4 b = *(const float4*)(src + i + 4);
    uint32_t h0, l0, h1, l1, h2, l2, h3, l3;
    split_pack2(a.x, a.y, h0, l0);
    split_pack2(a.z, a.w, h1, l1);
    split_pack2(b.x, b.y, h2, l2);
    split_pack2(b.z, b.w, h3, l3);
    *(uint4*)(h + i) = make_uint4(h0, h1, h2, h3);
    *(uint4*)(l + i) = make_uint4(l0, l1, l2, l3);
}

// ===========================================================================
// bf16-split HMMA NT GEMM — 512 threads, warp tile 32x32 (occupancy build).
// CTA 128x128, BK=32, 2-stage cp.async. 2 CTAs/SM -> 32 warps/SM.
// ===========================================================================
#define GS_ROW   80
#define GS_TILE  10240          // 128 * 80
#define GS_STAGE 40960          // 4 tiles
#define GEMM_SMEM (2 * GS_STAGE)

template <int MODE>
__global__ void __launch_bounds__(512, 2) gemm_hmma(float* __restrict__ Yout) {
    extern __shared__ char smem[];
    const uint32_t sb = smem_u32(smem);
    const int tid  = threadIdx.x;
    const int wid  = tid >> 5;
    const int lane = tid & 31;
    const int m0 = blockIdx.y * 128;
    const int n0 = blockIdx.x * 128;

    const __nv_bfloat16 *Ah, *Al, *Bh, *Bl;
    int z = 0;
    if (MODE == 0) {
        z  = blockIdx.z;
        Ah = g_INh + (size_t)z * MROWS * DMODEL;
        Al = g_INl + (size_t)z * MROWS * DMODEL;
        Bh = g_Wh + (size_t)z * DMODEL * DMODEL;
        Bl = g_Wl + (size_t)z * DMODEL * DMODEL;
    } else {
        Ah = g_CtxH; Al = g_CtxL;
        Bh = g_Wh + (size_t)3 * DMODEL * DMODEL;
        Bl = g_Wl + (size_t)3 * DMODEL * DMODEL;
    }

    // prefetch mapping: 512 threads, 128 rows x 4 16B-chunks per tile,
    // one chunk per thread per tile.
    const int prow = tid >> 2;
    const int pc   = tid & 3;
    const __nv_bfloat16* srcAh = Ah + (size_t)(m0 + prow) * DMODEL + pc * 8;
    const __nv_bfloat16* srcAl = Al + (size_t)(m0 + prow) * DMODEL + pc * 8;
    const __nv_bfloat16* srcBh = Bh + (size_t)(n0 + prow) * DMODEL + pc * 8;
    const __nv_bfloat16* srcBl = Bl + (size_t)(n0 + prow) * DMODEL + pc * 8;
    const uint32_t pdst = (uint32_t)prow * GS_ROW + pc * 16;

    auto prefetch = [&](int ks, int st) {
        const uint32_t s0 = sb + st * GS_STAGE + pdst;
        const int ko = ks * 32;
        CP16(s0 + 0 * GS_TILE, srcAh + ko);
        CP16(s0 + 1 * GS_TILE, srcAl + ko);
        CP16(s0 + 2 * GS_TILE, srcBh + ko);
        CP16(s0 + 3 * GS_TILE, srcBl + ko);
    };

    // mma fragment mapping: warp grid 4m x 4n, tile 32x32 per warp
    const int wm = (wid & 3) * 32;
    const int wn = (wid >> 2) * 32;
    const int aRow  = lane & 15;
    const int aColB = (lane >> 4) * 16;
    const int bRow  = ((lane >> 4) << 3) + (lane & 7);
    const int bColB = ((lane >> 3) & 1) * 16;
    const uint32_t aOff = (uint32_t)(wm + aRow) * GS_ROW + aColB;
    const uint32_t bOff = (uint32_t)(wn + bRow) * GS_ROW + bColB;

    float acc[2][4][4];
#pragma unroll
    for (int mt = 0; mt < 2; mt++)
#pragma unroll
        for (int nt = 0; nt < 4; nt++)
#pragma unroll
            for (int e = 0; e < 4; e++) acc[mt][nt][e] = 0.f;

    prefetch(0, 0);
    CP_COMMIT();

    for (int ks = 0; ks < 32; ks++) {
        CP_WAIT0();
        __syncthreads();
        if (ks < 31) {
            prefetch(ks + 1, (ks + 1) & 1);
            CP_COMMIT();
        }
        const uint32_t st = sb + (ks & 1) * GS_STAGE;
        const uint32_t aH = st + aOff;
        const uint32_t aL = st + GS_TILE + aOff;
        const uint32_t bH = st + 2 * GS_TILE + bOff;
        const uint32_t bL = st + 3 * GS_TILE + bOff;

#pragma unroll
        for (int k16 = 0; k16 < 2; k16++) {
            const uint32_t kb = k16 * 32;
            uint32_t AfH[2][4], AfL[2][4], BfH[2][4], BfL[2][4];
#pragma unroll
            for (int mt = 0; mt < 2; mt++) {
                LDSM_X4(AfH[mt], aH + mt * (16 * GS_ROW) + kb);
                LDSM_X4(AfL[mt], aL + mt * (16 * GS_ROW) + kb);
            }
#pragma unroll
            for (int p = 0; p < 2; p++) {
                LDSM_X4(BfH[p], bH + p * (16 * GS_ROW) + kb);
                LDSM_X4(BfL[p], bL + p * (16 * GS_ROW) + kb);
            }
#pragma unroll
            for (int mt = 0; mt < 2; mt++)
#pragma unroll
                for (int nt = 0; nt < 4; nt++) {
                    const int p = nt >> 1, q2 = (nt & 1) * 2;
                    mma_bf16(acc[mt][nt], AfH[mt], BfH[p][q2], BfH[p][q2 + 1]);
                    mma_bf16(acc[mt][nt], AfH[mt], BfL[p][q2], BfL[p][q2 + 1]);
                    mma_bf16(acc[mt][nt], AfL[mt], BfH[p][q2], BfH[p][q2 + 1]);
                }
        }
        __syncthreads();
    }

    // ---- epilogue ----
    __nv_bfloat16 *OH = nullptr, *OL = nullptr;
    if (MODE == 0) {
        OH = (z == 0) ? g_Qh : (z == 1) ? g_Kh : g_Vh;
        OL = (z == 0) ? g_Ql : (z == 1) ? g_Kl : g_Vl;
    }
    const int g  = lane >> 2;
    const int tq = lane & 3;
#pragma unroll
    for (int mt = 0; mt < 2; mt++) {
#pragma unroll
        for (int nt = 0; nt < 4; nt++) {
            const int mrow = m0 + wm + mt * 16 + g;
            const int ncol = n0 + wn + nt * 8 + tq * 2;
#pragma unroll
            for (int half = 0; half < 2; half++) {
                const int m = mrow + half * 8;
                const float v0 = acc[mt][nt][half * 2 + 0];
                const float v1 = acc[mt][nt][half * 2 + 1];
                if (MODE == 1) {
                    *(float2*)&Yout[(size_t)m * DMODEL + ncol] = make_float2(v0, v1);
                } else {
                    const int b  = m >> 11;
                    const int s  = m & (SEQ - 1);
                    const int h  = ncol >> 6;
                    const int dc = ncol & 63;
                    const size_t off = ((size_t)(b * NHEADS + h) * SEQ + s) * DK + dc;
                    uint32_t hi, lo;
                    split_pack2(v0, v1, hi, lo);
                    *(uint32_t*)&OH[off] = hi;
                    *(uint32_t*)&OL[off] = lo;
                }
            }
        }
    }
}

// ===========================================================================
// HMMA bf16-split causal flash attention (unchanged from round 6).
// ===========================================================================
#define BSTR     144
#define KV_TILE  (64 * BSTR)      // 9216
#define KV_STAGE (4 * KV_TILE)    // 36864
#define ATTN_SMEM (2 * KV_STAGE)  // 73728

__global__ void __launch_bounds__(256) attn_hmma() {
    extern __shared__ char smem[];
    const uint32_t sb = smem_u32(smem);

    const int tid  = threadIdx.x;
    const int wid  = tid >> 5;
    const int lane = tid & 31;
    const int g    = lane >> 2;
    const int tq   = lane & 3;
    const int qb   = gridDim.x - 1 - blockIdx.x;
    const int bh   = blockIdx.y;

    const size_t hbase = (size_t)bh * SEQ * DK;

    {
        const int row = tid >> 1;
        const int c0  = (tid & 1) * 4;
        const __nv_bfloat16* qh = g_Qh + hbase + (size_t)(qb * 128 + row) * DK + c0 * 8;
        const __nv_bfloat16* ql = g_Ql + hbase + (size_t)(qb * 128 + row) * DK + c0 * 8;
        const uint32_t dh = sb + (uint32_t)row * BSTR + c0 * 16;
        const uint32_t dl = dh + 128 * BSTR;
#pragma unroll
        for (int c = 0; c < 4; c++) {
            CP16(dh + c * 16, qh + c * 8);
            CP16(dl + c * 16, ql + c * 8);
        }
        CP_COMMIT();
    }
    CP_WAIT0();
    __syncthreads();

    uint32_t Qh[4][4], Ql[4][4];
    {
        const uint32_t qlane = (uint32_t)(wid * 16 + (lane & 15)) * BSTR +
                               (uint32_t)(lane >> 4) * 16;
#pragma unroll
        for (int ks = 0; ks < 4; ks++) {
            LDSM_X4(Qh[ks], sb + qlane + ks * 32);
            LDSM_X4(Ql[ks], sb + 128 * BSTR + qlane + ks * 32);
        }
    }
    __syncthreads();

    const int krow = tid >> 2;
    const int kc0  = (tid & 3) * 2;
    const __nv_bfloat16* sKh = g_Kh + hbase + (size_t)krow * DK + kc0 * 8;
    const __nv_bfloat16* sKl = g_Kl + hbase + (size_t)krow * DK + kc0 * 8;
    const __nv_bfloat16* sVh = g_Vh + hbase + (size_t)krow * DK + kc0 * 8;
    const __nv_bfloat16* sVl = g_Vl + hbase + (size_t)krow * DK + kc0 * 8;
    const uint32_t kdst = (uint32_t)krow * BSTR + kc0 * 16;

    auto prefetchKV = [&](int kb, int st) {
        const uint32_t s0 = sb + st * KV_STAGE + kdst;
        const size_t ko = (size_t)kb * 64 * DK;
#pragma unroll
        for (int c = 0; c < 2; c++) {
            CP16(s0 + 0 * KV_TILE + c * 16, sKh + ko + c * 8);
            CP16(s0 + 1 * KV_TILE + c * 16, sKl + ko + c * 8);
            CP16(s0 + 2 * KV_TILE + c * 16, sVh + ko + c * 8);
            CP16(s0 + 3 * KV_TILE + c * 16, sVl + ko + c * 8);
        }
    };

    const uint32_t k_lane = (uint32_t)((((lane >> 4) & 1) * 8 + (lane & 7))) * BSTR +
                            (uint32_t)((lane >> 3) & 1) * 16;
    const uint32_t v_lane = (uint32_t)((((lane >> 3) & 1) * 8 + (lane & 7))) * BSTR +
                            (uint32_t)((lane >> 4) & 1) * 16;

    float o[8][4];
#pragma unroll
    for (int nt = 0; nt < 8; nt++)
#pragma unroll
        for (int e = 0; e < 4; e++) o[nt][e] = 0.f;
    float m0 = -1e30f, m1 = -1e30f, l0 = 0.f, l1 = 0.f;

    const int row0 = qb * 128 + wid * 16 + g;
    const int kb_end = 2 * qb + 1;

    prefetchKV(0, 0);
    CP_COMMIT();

    for (int kb = 0; kb <= kb_end; kb++) {
        CP_WAIT0();
        __syncthreads();
        if (kb < kb_end) {
            prefetchKV(kb + 1, (kb + 1) & 1);
            CP_COMMIT();
        }
        const uint32_t st = sb + (kb & 1) * KV_STAGE;

        float s[8][4];
#pragma unroll
        for (int nt = 0; nt < 8; nt++)
#pragma unroll
            for (int e = 0; e < 4; e++) s[nt][e] = 0.f;

#pragma unroll
        for (int ks = 0; ks < 4; ks++) {
#pragma unroll
            for (int np = 0; np < 4; np++) {
                const uint32_t ka = (uint32_t)(np * 16) * BSTR + ks * 32 + k_lane;
                uint32_t KBh[4], KBl[4];
                LDSM_X4(KBh, st + ka);
                LDSM_X4(KBl, st + KV_TILE + ka);
                mma_bf16(s[2*np],   Qh[ks], KBh[0], KBh[1]);
                mma_bf16(s[2*np+1], Qh[ks], KBh[2], KBh[3]);
                mma_bf16(s[2*np],   Qh[ks], KBl[0], KBl[1]);
                mma_bf16(s[2*np+1], Qh[ks], KBl[2], KBl[3]);
                mma_bf16(s[2*np],   Ql[ks], KBh[0], KBh[1]);
                mma_bf16(s[2*np+1], Ql[ks], KBh[2], KBh[3]);
            }
        }

#pragma unroll
        for (int nt = 0; nt < 8; nt++)
#pragma unroll
            for (int e = 0; e < 4; e++) s[nt][e] *= 0.125f;

        if (kb >= 2 * qb) {
            const int cb = kb * 64 + 2 * tq;
#pragma unroll
            for (int nt = 0; nt < 8; nt++) {
                const int c = cb + nt * 8;
                if (c     > row0)     s[nt][0] = -1e9f;
                if (c + 1 > row0)     s[nt][1] = -1e9f;
                if (c     > row0 + 8) s[nt][2] = -1e9f;
                if (c + 1 > row0 + 8) s[nt][3] = -1e9f;
            }
        }

        float rm0 = -1e30f, rm1 = -1e30f;
#pragma unroll
        for (int nt = 0; nt < 8; nt++) {
            rm0 = fmaxf(rm0, fmaxf(s[nt][0], s[nt][1]));
            rm1 = fmaxf(rm1, fmaxf(s[nt][2], s[nt][3]));
        }
        rm0 = fmaxf(rm0, __shfl_xor_sync(0xffffffffu, rm0, 1));
        rm0 = fmaxf(rm0, __shfl_xor_sync(0xffffffffu, rm0, 2));
        rm1 = fmaxf(rm1, __shfl_xor_sync(0xffffffffu, rm1, 1));
        rm1 = fmaxf(rm1, __shfl_xor_sync(0xffffffffu, rm1, 2));

        const float nm0 = fmaxf(m0, rm0);
        const float nm1 = fmaxf(m1, rm1);
        const float c0 = __expf(m0 - nm0);
        const float c1 = __expf(m1 - nm1);
        m0 = nm0; m1 = nm1;

        float rs0 = 0.f, rs1 = 0.f;
#pragma unroll
        for (int nt = 0; nt < 8; nt++) {
            s[nt][0] = __expf(s[nt][0] - nm0); rs0 += s[nt][0];
            s[nt][1] = __expf(s[nt][1] - nm0); rs0 += s[nt][1];
            s[nt][2] = __expf(s[nt][2] - nm1); rs1 += s[nt][2];
            s[nt][3] = __expf(s[nt][3] - nm1); rs1 += s[nt][3];
        }
        rs0 += __shfl_xor_sync(0xffffffffu, rs0, 1);
        rs0 += __shfl_xor_sync(0xffffffffu, rs0, 2);
        rs1 += __shfl_xor_sync(0xffffffffu, rs1, 1);
        rs1 += __shfl_xor_sync(0xffffffffu, rs1, 2);
        l0 = l0 * c0 + rs0;
        l1 = l1 * c1 + rs1;

#pragma unroll
        for (int nt = 0; nt < 8; nt++) {
            o[nt][0] *= c0; o[nt][1] *= c0;
            o[nt][2] *= c1; o[nt][3] *= c1;
        }

#pragma unroll
        for (int kt = 0; kt < 4; kt++) {
            uint32_t PAh[4], PAl[4];
            split_pack2(s[2*kt][0],   s[2*kt][1],   PAh[0], PAl[0]);
            split_pack2(s[2*kt][2],   s[2*kt][3],   PAh[1], PAl[1]);
            split_pack2(s[2*kt+1][0], s[2*kt+1][1], PAh[2], PAl[2]);
            split_pack2(s[2*kt+1][2], s[2*kt+1][3], PAh[3], PAl[3]);
#pragma unroll
            for (int dp = 0; dp < 4; dp++) {
                const uint32_t va = (uint32_t)(kt * 16) * BSTR + dp * 32 + v_lane;
                uint32_t VBh[4], VBl[4];
                LDSM_X4_T(VBh, st + 2 * KV_TILE + va);
                LDSM_X4_T(VBl, st + 3 * KV_TILE + va);
                mma_bf16(o[2*dp],   PAh, VBh[0], VBh[1]);
                mma_bf16(o[2*dp+1], PAh, VBh[2], VBh[3]);
                mma_bf16(o[2*dp],   PAh, VBl[0], VBl[1]);
                mma_bf16(o[2*dp+1], PAh, VBl[2], VBl[3]);
                mma_bf16(o[2*dp],   PAl, VBh[0], VBh[1]);
                mma_bf16(o[2*dp+1], PAl, VBh[2], VBh[3]);
            }
        }
        __syncthreads();
    }

    const int b = bh >> 4;
    const int h = bh & 15;
    const float i0 = 1.f / l0;
    const float i1 = 1.f / l1;
    const size_t off0 = ((size_t)(b * SEQ + row0))     * DMODEL + h * DK + tq * 2;
    const size_t off1 = ((size_t)(b * SEQ + row0 + 8)) * DMODEL + h * DK + tq * 2;
#pragma unroll
    for (int nt = 0; nt < 8; nt++) {
        uint32_t hi, lo;
        split_pack2(o[nt][0] * i0, o[nt][1] * i0, hi, lo);
        *(uint32_t*)&g_CtxH[off0 + nt * 8] = hi;
        *(uint32_t*)&g_CtxL[off0 + nt * 8] = lo;
        split_pack2(o[nt][2] * i1, o[nt][3] * i1, hi, lo);
        *(uint32_t*)&g_CtxH[off1 + nt * 8] = hi;
        *(uint32_t*)&g_CtxL[off1 + nt * 8] = lo;
    }
}

// ---------------------------------------------------------------------------
extern "C" void kernel_launch(void* const* d_in, const int* in_sizes, int n_in,
                              void* d_out, int out_size) {
    const float* q  = (const float*)d_in[0];
    const float* k  = (const float*)d_in[1];
    const float* v  = (const float*)d_in[2];
    const float* wq = (const float*)d_in[3];
    const float* wk = (const float*)d_in[4];
    const float* wv = (const float*)d_in[5];
    const float* wo = (const float*)d_in[6];
    float* out = (float*)d_out;

    static int configured = 0;
    if (!configured) {
        cudaFuncSetAttribute(gemm_hmma<0>, cudaFuncAttributeMaxDynamicSharedMemorySize, GEMM_SMEM);
        cudaFuncSetAttribute(gemm_hmma<1>, cudaFuncAttributeMaxDynamicSharedMemorySize, GEMM_SMEM);
        cudaFuncSetAttribute(attn_hmma, cudaFuncAttributeMaxDynamicSharedMemorySize, ATTN_SMEM);
        configured = 1;
    }

    dim3 gs(MROWS * DMODEL / (256 * 8), 7);    // (4096, 7)
    ksplit<<<gs, 256>>>(q, k, v, wq, wk, wv, wo);

    dim3 gqkv(DMODEL / 128, MROWS / 128, 3);   // (8, 64, 3)
    gemm_hmma<0><<<gqkv, 512, GEMM_SMEM>>>(nullptr);

    dim3 ga(SEQ / 128, BATCH * NHEADS);        // (16, 64)
    attn_hmma<<<ga, 256, ATTN_SMEM>>>();

    dim3 go(DMODEL / 128, MROWS / 128);        // (8, 64)
    gemm_hmma<1><<<go, 512, GEMM_SMEM>>>(out);
}

// round 8
// speedup vs baseline: 3.2393x; 1.2490x over previous
#include <cuda_runtime.h>
#include <cuda_bf16.h>
#include <cuda_fp16.h>
#include <cstdint>

#define BATCH   4
#define SEQ     2048
#define DMODEL  1024
#define NHEADS  16
#define DK      64
#define MROWS   (BATCH * SEQ)                 // 8192
#define HEADELEMS (BATCH * NHEADS * SEQ * DK) // 8M

// ---------------- persistent scratch ---------------------------------------
// GEMM side: fp16 split activations + single-rounded fp16 weights.
__device__ __half g_INh[3 * MROWS * DMODEL];
__device__ __half g_INl[3 * MROWS * DMODEL];
__device__ __half g_W[4 * DMODEL * DMODEL];
__device__ __half g_CtxH[MROWS * DMODEL], g_CtxL[MROWS * DMODEL];
// Attention side: bf16 hi/lo Q/K/V (3-product path unchanged).
__device__ __nv_bfloat16 g_Qh[HEADELEMS], g_Ql[HEADELEMS];
__device__ __nv_bfloat16 g_Kh[HEADELEMS], g_Kl[HEADELEMS];
__device__ __nv_bfloat16 g_Vh[HEADELEMS], g_Vl[HEADELEMS];

// ============================ helpers ======================================
__device__ __forceinline__ uint32_t smem_u32(const void* p) {
    uint32_t a;
    asm("{ .reg .u64 t; cvta.to.shared.u64 t, %1; cvt.u32.u64 %0, t; }"
        : "=r"(a) : "l"(p));
    return a;
}
#define LDSM_X4(r, addr) \
    asm volatile("ldmatrix.sync.aligned.m8n8.x4.shared.b16 {%0,%1,%2,%3}, [%4];" \
        : "=r"((r)[0]), "=r"((r)[1]), "=r"((r)[2]), "=r"((r)[3]) : "r"(addr))
#define LDSM_X4_T(r, addr) \
    asm volatile("ldmatrix.sync.aligned.m8n8.x4.trans.shared.b16 {%0,%1,%2,%3}, [%4];" \
        : "=r"((r)[0]), "=r"((r)[1]), "=r"((r)[2]), "=r"((r)[3]) : "r"(addr))
#define CP16(dst, src) \
    asm volatile("cp.async.cg.shared.global [%0], [%1], 16;" \
                 :: "r"(dst), "l"(src) : "memory")
#define CP_COMMIT() asm volatile("cp.async.commit_group;" ::: "memory")
#define CP_WAIT0()  asm volatile("cp.async.wait_group 0;" ::: "memory")

__device__ __forceinline__ void mma_bf16(float* c, const uint32_t* a,
                                         uint32_t b0, uint32_t b1) {
    asm volatile("mma.sync.aligned.m16n8k16.row.col.f32.bf16.bf16.f32 "
        "{%0,%1,%2,%3}, {%4,%5,%6,%7}, {%8,%9}, {%0,%1,%2,%3};"
        : "+f"(c[0]), "+f"(c[1]), "+f"(c[2]), "+f"(c[3])
        : "r"(a[0]), "r"(a[1]), "r"(a[2]), "r"(a[3]), "r"(b0), "r"(b1));
}
__device__ __forceinline__ void mma_f16(float* c, const uint32_t* a,
                                        uint32_t b0, uint32_t b1) {
    asm volatile("mma.sync.aligned.m16n8k16.row.col.f32.f16.f16.f32 "
        "{%0,%1,%2,%3}, {%4,%5,%6,%7}, {%8,%9}, {%0,%1,%2,%3};"
        : "+f"(c[0]), "+f"(c[1]), "+f"(c[2]), "+f"(c[3])
        : "r"(a[0]), "r"(a[1]), "r"(a[2]), "r"(a[3]), "r"(b0), "r"(b1));
}

// bf16 2-term split (attention path, unchanged)
__device__ __forceinline__ void split_pack2(float x, float y,
                                            uint32_t& hi, uint32_t& lo) {
    __nv_bfloat162 h = __floats2bfloat162_rn(x, y);
    const float rx = x - __bfloat162float(__low2bfloat16(h));
    const float ry = y - __bfloat162float(__high2bfloat16(h));
    __nv_bfloat162 l = __floats2bfloat162_rn(rx, ry);
    hi = *reinterpret_cast<uint32_t*>(&h);
    lo = *reinterpret_cast<uint32_t*>(&l);
}
// fp16 2-term split (GEMM activations / ctx)
__device__ __forceinline__ void split_pack2_f16(float x, float y,
                                                uint32_t& hi, uint32_t& lo) {
    __half2 h = __floats2half2_rn(x, y);
    const float rx = x - __half2float(__low2half(h));
    const float ry = y - __half2float(__high2half(h));
    __half2 l = __floats2half2_rn(rx, ry);
    hi = *reinterpret_cast<uint32_t*>(&h);
    lo = *reinterpret_cast<uint32_t*>(&l);
}

// ===========================================================================
// Pre-split pass. y 0-2: inputs -> fp16 hi/lo. y 3-6: weights -> fp16 single.
// ===========================================================================
__global__ void __launch_bounds__(256) ksplit(
    const float* __restrict__ q, const float* __restrict__ k,
    const float* __restrict__ v, const float* __restrict__ wq,
    const float* __restrict__ wk, const float* __restrict__ wv,
    const float* __restrict__ wo) {
    const int sel = blockIdx.y;
    const int i = (blockIdx.x * 256 + threadIdx.x) * 8;
    if (sel < 3) {
        const float* src = (sel == 0) ? q : (sel == 1) ? k : v;
        __half* h = g_INh + (size_t)sel * MROWS * DMODEL;
        __half* l = g_INl + (size_t)sel * MROWS * DMODEL;
        const float4 a = *(const float4*)(src + i);
        const float4 b = *(const float4*)(src + i + 4);
        uint32_t h0, l0, h1, l1, h2, l2, h3, l3;
        split_pack2_f16(a.x, a.y, h0, l0);
        split_pack2_f16(a.z, a.w, h1, l1);
        split_pack2_f16(b.x, b.y, h2, l2);
        split_pack2_f16(b.z, b.w, h3, l3);
        *(uint4*)(h + i) = make_uint4(h0, h1, h2, h3);
        *(uint4*)(l + i) = make_uint4(l0, l1, l2, l3);
    } else {
        const int w = sel - 3;
        if (i >= DMODEL * DMODEL) return;
        const float* src = (w == 0) ? wq : (w == 1) ? wk : (w == 2) ? wv : wo;
        __half* h = g_W + (size_t)w * DMODEL * DMODEL;
        const float4 a = *(const float4*)(src + i);
        const float4 b = *(const float4*)(src + i + 4);
        __half2 h0 = __floats2half2_rn(a.x, a.y);
        __half2 h1 = __floats2half2_rn(a.z, a.w);
        __half2 h2 = __floats2half2_rn(b.x, b.y);
        __half2 h3 = __floats2half2_rn(b.z, b.w);
        *(uint4*)(h + i) = make_uint4(*(uint32_t*)&h0, *(uint32_t*)&h1,
                                      *(uint32_t*)&h2, *(uint32_t*)&h3);
    }
}

// ===========================================================================
// fp16 2-product HMMA NT GEMM: Y = A @ B^T, A split (hi/lo), B single fp16.
// 512 threads, warp tile 32x32, CTA 128x128, BK=32, 2-stage cp.async.
// ===========================================================================
#define GS_ROW   80
#define GS_TILE  10240          // 128 * 80
#define GS_STAGE (3 * GS_TILE)  // Ah, Al, B
#define GEMM_SMEM (2 * GS_STAGE)

template <int MODE>
__global__ void __launch_bounds__(512, 2) gemm_hmma(float* __restrict__ Yout) {
    extern __shared__ char smem[];
    const uint32_t sb = smem_u32(smem);
    const int tid  = threadIdx.x;
    const int wid  = tid >> 5;
    const int lane = tid & 31;
    const int m0 = blockIdx.y * 128;
    const int n0 = blockIdx.x * 128;

    const __half *Ah, *Al, *Bw;
    int z = 0;
    if (MODE == 0) {
        z  = blockIdx.z;
        Ah = g_INh + (size_t)z * MROWS * DMODEL;
        Al = g_INl + (size_t)z * MROWS * DMODEL;
        Bw = g_W + (size_t)z * DMODEL * DMODEL;
    } else {
        Ah = g_CtxH; Al = g_CtxL;
        Bw = g_W + (size_t)3 * DMODEL * DMODEL;
    }

    // prefetch: 512 threads, 128 rows x 4 chunks, one 16B chunk per tile each
    const int prow = tid >> 2;
    const int pc   = tid & 3;
    const __half* srcAh = Ah + (size_t)(m0 + prow) * DMODEL + pc * 8;
    const __half* srcAl = Al + (size_t)(m0 + prow) * DMODEL + pc * 8;
    const __half* srcB  = Bw + (size_t)(n0 + prow) * DMODEL + pc * 8;
    const uint32_t pdst = (uint32_t)prow * GS_ROW + pc * 16;

    auto prefetch = [&](int ks, int st) {
        const uint32_t s0 = sb + st * GS_STAGE + pdst;
        const int ko = ks * 32;
        CP16(s0 + 0 * GS_TILE, srcAh + ko);
        CP16(s0 + 1 * GS_TILE, srcAl + ko);
        CP16(s0 + 2 * GS_TILE, srcB + ko);
    };

    // warp grid 4m x 4n, tile 32x32 per warp
    const int wm = (wid & 3) * 32;
    const int wn = (wid >> 2) * 32;
    const int aRow  = lane & 15;
    const int aColB = (lane >> 4) * 16;
    const int bRow  = ((lane >> 4) << 3) + (lane & 7);
    const int bColB = ((lane >> 3) & 1) * 16;
    const uint32_t aOff = (uint32_t)(wm + aRow) * GS_ROW + aColB;
    const uint32_t bOff = (uint32_t)(wn + bRow) * GS_ROW + bColB;

    float acc[2][4][4];
#pragma unroll
    for (int mt = 0; mt < 2; mt++)
#pragma unroll
        for (int nt = 0; nt < 4; nt++)
#pragma unroll
            for (int e = 0; e < 4; e++) acc[mt][nt][e] = 0.f;

    prefetch(0, 0);
    CP_COMMIT();

    for (int ks = 0; ks < 32; ks++) {
        CP_WAIT0();
        __syncthreads();
        if (ks < 31) {
            prefetch(ks + 1, (ks + 1) & 1);
            CP_COMMIT();
        }
        const uint32_t st = sb + (ks & 1) * GS_STAGE;
        const uint32_t aH = st + aOff;
        const uint32_t aL = st + GS_TILE + aOff;
        const uint32_t bB = st + 2 * GS_TILE + bOff;

#pragma unroll
        for (int k16 = 0; k16 < 2; k16++) {
            const uint32_t kb = k16 * 32;
            uint32_t AfH[2][4], AfL[2][4], Bf[2][4];
#pragma unroll
            for (int mt = 0; mt < 2; mt++) {
                LDSM_X4(AfH[mt], aH + mt * (16 * GS_ROW) + kb);
                LDSM_X4(AfL[mt], aL + mt * (16 * GS_ROW) + kb);
            }
#pragma unroll
            for (int p = 0; p < 2; p++)
                LDSM_X4(Bf[p], bB + p * (16 * GS_ROW) + kb);
#pragma unroll
            for (int mt = 0; mt < 2; mt++)
#pragma unroll
                for (int nt = 0; nt < 4; nt++) {
                    const int p = nt >> 1, q2 = (nt & 1) * 2;
                    mma_f16(acc[mt][nt], AfH[mt], Bf[p][q2], Bf[p][q2 + 1]);
                    mma_f16(acc[mt][nt], AfL[mt], Bf[p][q2], Bf[p][q2 + 1]);
                }
        }
        __syncthreads();
    }

    // ---- epilogue ----
    __nv_bfloat16 *OH = nullptr, *OL = nullptr;
    if (MODE == 0) {
        OH = (z == 0) ? g_Qh : (z == 1) ? g_Kh : g_Vh;
        OL = (z == 0) ? g_Ql : (z == 1) ? g_Kl : g_Vl;
    }
    const int g  = lane >> 2;
    const int tq = lane & 3;
#pragma unroll
    for (int mt = 0; mt < 2; mt++) {
#pragma unroll
        for (int nt = 0; nt < 4; nt++) {
            const int mrow = m0 + wm + mt * 16 + g;
            const int ncol = n0 + wn + nt * 8 + tq * 2;
#pragma unroll
            for (int half = 0; half < 2; half++) {
                const int m = mrow + half * 8;
                const float v0 = acc[mt][nt][half * 2 + 0];
                const float v1 = acc[mt][nt][half * 2 + 1];
                if (MODE == 1) {
                    *(float2*)&Yout[(size_t)m * DMODEL + ncol] = make_float2(v0, v1);
                } else {
                    const int b  = m >> 11;
                    const int s  = m & (SEQ - 1);
                    const int h  = ncol >> 6;
                    const int dc = ncol & 63;
                    const size_t off = ((size_t)(b * NHEADS + h) * SEQ + s) * DK + dc;
                    uint32_t hi, lo;
                    split_pack2(v0, v1, hi, lo);
                    *(uint32_t*)&OH[off] = hi;
                    *(uint32_t*)&OL[off] = lo;
                }
            }
        }
    }
}

// ===========================================================================
// HMMA bf16-split causal flash attention (mainloop unchanged; epilogue ->
// fp16 hi/lo ctx for the Wo GEMM).
// ===========================================================================
#define BSTR     144
#define KV_TILE  (64 * BSTR)      // 9216
#define KV_STAGE (4 * KV_TILE)    // 36864
#define ATTN_SMEM (2 * KV_STAGE)  // 73728

__global__ void __launch_bounds__(256) attn_hmma() {
    extern __shared__ char smem[];
    const uint32_t sb = smem_u32(smem);

    const int tid  = threadIdx.x;
    const int wid  = tid >> 5;
    const int lane = tid & 31;
    const int g    = lane >> 2;
    const int tq   = lane & 3;
    const int qb   = gridDim.x - 1 - blockIdx.x;
    const int bh   = blockIdx.y;

    const size_t hbase = (size_t)bh * SEQ * DK;

    {
        const int row = tid >> 1;
        const int c0  = (tid & 1) * 4;
        const __nv_bfloat16* qh = g_Qh + hbase + (size_t)(qb * 128 + row) * DK + c0 * 8;
        const __nv_bfloat16* ql = g_Ql + hbase + (size_t)(qb * 128 + row) * DK + c0 * 8;
        const uint32_t dh = sb + (uint32_t)row * BSTR + c0 * 16;
        const uint32_t dl = dh + 128 * BSTR;
#pragma unroll
        for (int c = 0; c < 4; c++) {
            CP16(dh + c * 16, qh + c * 8);
            CP16(dl + c * 16, ql + c * 8);
        }
        CP_COMMIT();
    }
    CP_WAIT0();
    __syncthreads();

    uint32_t Qh[4][4], Ql[4][4];
    {
        const uint32_t qlane = (uint32_t)(wid * 16 + (lane & 15)) * BSTR +
                               (uint32_t)(lane >> 4) * 16;
#pragma unroll
        for (int ks = 0; ks < 4; ks++) {
            LDSM_X4(Qh[ks], sb + qlane + ks * 32);
            LDSM_X4(Ql[ks], sb + 128 * BSTR + qlane + ks * 32);
        }
    }
    __syncthreads();

    const int krow = tid >> 2;
    const int kc0  = (tid & 3) * 2;
    const __nv_bfloat16* sKh = g_Kh + hbase + (size_t)krow * DK + kc0 * 8;
    const __nv_bfloat16* sKl = g_Kl + hbase + (size_t)krow * DK + kc0 * 8;
    const __nv_bfloat16* sVh = g_Vh + hbase + (size_t)krow * DK + kc0 * 8;
    const __nv_bfloat16* sVl = g_Vl + hbase + (size_t)krow * DK + kc0 * 8;
    const uint32_t kdst = (uint32_t)krow * BSTR + kc0 * 16;

    auto prefetchKV = [&](int kb, int st) {
        const uint32_t s0 = sb + st * KV_STAGE + kdst;
        const size_t ko = (size_t)kb * 64 * DK;
#pragma unroll
        for (int c = 0; c < 2; c++) {
            CP16(s0 + 0 * KV_TILE + c * 16, sKh + ko + c * 8);
            CP16(s0 + 1 * KV_TILE + c * 16, sKl + ko + c * 8);
            CP16(s0 + 2 * KV_TILE + c * 16, sVh + ko + c * 8);
            CP16(s0 + 3 * KV_TILE + c * 16, sVl + ko + c * 8);
        }
    };

    const uint32_t k_lane = (uint32_t)((((lane >> 4) & 1) * 8 + (lane & 7))) * BSTR +
                            (uint32_t)((lane >> 3) & 1) * 16;
    const uint32_t v_lane = (uint32_t)((((lane >> 3) & 1) * 8 + (lane & 7))) * BSTR +
                            (uint32_t)((lane >> 4) & 1) * 16;

    float o[8][4];
#pragma unroll
    for (int nt = 0; nt < 8; nt++)
#pragma unroll
        for (int e = 0; e < 4; e++) o[nt][e] = 0.f;
    float m0 = -1e30f, m1 = -1e30f, l0 = 0.f, l1 = 0.f;

    const int row0 = qb * 128 + wid * 16 + g;
    const int kb_end = 2 * qb + 1;

    prefetchKV(0, 0);
    CP_COMMIT();

    for (int kb = 0; kb <= kb_end; kb++) {
        CP_WAIT0();
        __syncthreads();
        if (kb < kb_end) {
            prefetchKV(kb + 1, (kb + 1) & 1);
            CP_COMMIT();
        }
        const uint32_t st = sb + (kb & 1) * KV_STAGE;

        float s[8][4];
#pragma unroll
        for (int nt = 0; nt < 8; nt++)
#pragma unroll
            for (int e = 0; e < 4; e++) s[nt][e] = 0.f;

#pragma unroll
        for (int ks = 0; ks < 4; ks++) {
#pragma unroll
            for (int np = 0; np < 4; np++) {
                const uint32_t ka = (uint32_t)(np * 16) * BSTR + ks * 32 + k_lane;
                uint32_t KBh[4], KBl[4];
                LDSM_X4(KBh, st + ka);
                LDSM_X4(KBl, st + KV_TILE + ka);
                mma_bf16(s[2*np],   Qh[ks], KBh[0], KBh[1]);
                mma_bf16(s[2*np+1], Qh[ks], KBh[2], KBh[3]);
                mma_bf16(s[2*np],   Qh[ks], KBl[0], KBl[1]);
                mma_bf16(s[2*np+1], Qh[ks], KBl[2], KBl[3]);
                mma_bf16(s[2*np],   Ql[ks], KBh[0], KBh[1]);
                mma_bf16(s[2*np+1], Ql[ks], KBh[2], KBh[3]);
            }
        }

#pragma unroll
        for (int nt = 0; nt < 8; nt++)
#pragma unroll
            for (int e = 0; e < 4; e++) s[nt][e] *= 0.125f;

        if (kb >= 2 * qb) {
            const int cb = kb * 64 + 2 * tq;
#pragma unroll
            for (int nt = 0; nt < 8; nt++) {
                const int c = cb + nt * 8;
                if (c     > row0)     s[nt][0] = -1e9f;
                if (c + 1 > row0)     s[nt][1] = -1e9f;
                if (c     > row0 + 8) s[nt][2] = -1e9f;
                if (c + 1 > row0 + 8) s[nt][3] = -1e9f;
            }
        }

        float rm0 = -1e30f, rm1 = -1e30f;
#pragma unroll
        for (int nt = 0; nt < 8; nt++) {
            rm0 = fmaxf(rm0, fmaxf(s[nt][0], s[nt][1]));
            rm1 = fmaxf(rm1, fmaxf(s[nt][2], s[nt][3]));
        }
        rm0 = fmaxf(rm0, __shfl_xor_sync(0xffffffffu, rm0, 1));
        rm0 = fmaxf(rm0, __shfl_xor_sync(0xffffffffu, rm0, 2));
        rm1 = fmaxf(rm1, __shfl_xor_sync(0xffffffffu, rm1, 1));
        rm1 = fmaxf(rm1, __shfl_xor_sync(0xffffffffu, rm1, 2));

        const float nm0 = fmaxf(m0, rm0);
        const float nm1 = fmaxf(m1, rm1);
        const float c0 = __expf(m0 - nm0);
        const float c1 = __expf(m1 - nm1);
        m0 = nm0; m1 = nm1;

        float rs0 = 0.f, rs1 = 0.f;
#pragma unroll
        for (int nt = 0; nt < 8; nt++) {
            s[nt][0] = __expf(s[nt][0] - nm0); rs0 += s[nt][0];
            s[nt][1] = __expf(s[nt][1] - nm0); rs0 += s[nt][1];
            s[nt][2] = __expf(s[nt][2] - nm1); rs1 += s[nt][2];
            s[nt][3] = __expf(s[nt][3] - nm1); rs1 += s[nt][3];
        }
        rs0 += __shfl_xor_sync(0xffffffffu, rs0, 1);
        rs0 += __shfl_xor_sync(0xffffffffu, rs0, 2);
        rs1 += __shfl_xor_sync(0xffffffffu, rs1, 1);
        rs1 += __shfl_xor_sync(0xffffffffu, rs1, 2);
        l0 = l0 * c0 + rs0;
        l1 = l1 * c1 + rs1;

#pragma unroll
        for (int nt = 0; nt < 8; nt++) {
            o[nt][0] *= c0; o[nt][1] *= c0;
            o[nt][2] *= c1; o[nt][3] *= c1;
        }

#pragma unroll
        for (int kt = 0; kt < 4; kt++) {
            uint32_t PAh[4], PAl[4];
            split_pack2(s[2*kt][0],   s[2*kt][1],   PAh[0], PAl[0]);
            split_pack2(s[2*kt][2],   s[2*kt][3],   PAh[1], PAl[1]);
            split_pack2(s[2*kt+1][0], s[2*kt+1][1], PAh[2], PAl[2]);
            split_pack2(s[2*kt+1][2], s[2*kt+1][3], PAh[3], PAl[3]);
#pragma unroll
            for (int dp = 0; dp < 4; dp++) {
                const uint32_t va = (uint32_t)(kt * 16) * BSTR + dp * 32 + v_lane;
                uint32_t VBh[4], VBl[4];
                LDSM_X4_T(VBh, st + 2 * KV_TILE + va);
                LDSM_X4_T(VBl, st + 3 * KV_TILE + va);
                mma_bf16(o[2*dp],   PAh, VBh[0], VBh[1]);
                mma_bf16(o[2*dp+1], PAh, VBh[2], VBh[3]);
                mma_bf16(o[2*dp],   PAh, VBl[0], VBl[1]);
                mma_bf16(o[2*dp+1], PAh, VBl[2], VBl[3]);
                mma_bf16(o[2*dp],   PAl, VBh[0], VBh[1]);
                mma_bf16(o[2*dp+1], PAl, VBh[2], VBh[3]);
            }
        }
        __syncthreads();
    }

    // ---- normalize + fp16 split-store ctx for the Wo GEMM ----
    const int b = bh >> 4;
    const int h = bh & 15;
    const float i0 = 1.f / l0;
    const float i1 = 1.f / l1;
    const size_t off0 = ((size_t)(b * SEQ + row0))     * DMODEL + h * DK + tq * 2;
    const size_t off1 = ((size_t)(b * SEQ + row0 + 8)) * DMODEL + h * DK + tq * 2;
#pragma unroll
    for (int nt = 0; nt < 8; nt++) {
        uint32_t hi, lo;
        split_pack2_f16(o[nt][0] * i0, o[nt][1] * i0, hi, lo);
        *(uint32_t*)&g_CtxH[off0 + nt * 8] = hi;
        *(uint32_t*)&g_CtxL[off0 + nt * 8] = lo;
        split_pack2_f16(o[nt][2] * i1, o[nt][3] * i1, hi, lo);
        *(uint32_t*)&g_CtxH[off1 + nt * 8] = hi;
        *(uint32_t*)&g_CtxL[off1 + nt * 8] = lo;
    }
}

// ---------------------------------------------------------------------------
extern "C" void kernel_launch(void* const* d_in, const int* in_sizes, int n_in,
                              void* d_out, int out_size) {
    const float* q  = (const float*)d_in[0];
    const float* k  = (const float*)d_in[1];
    const float* v  = (const float*)d_in[2];
    const float* wq = (const float*)d_in[3];
    const float* wk = (const float*)d_in[4];
    const float* wv = (const float*)d_in[5];
    const float* wo = (const float*)d_in[6];
    float* out = (float*)d_out;

    static int configured = 0;
    if (!configured) {
        cudaFuncSetAttribute(gemm_hmma<0>, cudaFuncAttributeMaxDynamicSharedMemorySize, GEMM_SMEM);
        cudaFuncSetAttribute(gemm_hmma<1>, cudaFuncAttributeMaxDynamicSharedMemorySize, GEMM_SMEM);
        cudaFuncSetAttribute(attn_hmma, cudaFuncAttributeMaxDynamicSharedMemorySize, ATTN_SMEM);
        configured = 1;
    }

    dim3 gs(MROWS * DMODEL / (256 * 8), 7);    // (4096, 7)
    ksplit<<<gs, 256>>>(q, k, v, wq, wk, wv, wo);

    dim3 gqkv(DMODEL / 128, MROWS / 128, 3);   // (8, 64, 3)
    gemm_hmma<0><<<gqkv, 512, GEMM_SMEM>>>(nullptr);

    dim3 ga(SEQ / 128, BATCH * NHEADS);        // (16, 64)
    attn_hmma<<<ga, 256, ATTN_SMEM>>>();

    dim3 go(DMODEL / 128, MROWS / 128);        // (8, 64)
    gemm_hmma<1><<<go, 512, GEMM_SMEM>>>(out);
}

// round 9
// speedup vs baseline: 3.2515x; 1.0038x over previous
#include <cuda_runtime.h>
#include <cuda_bf16.h>
#include <cuda_fp16.h>
#include <cstdint>

#define BATCH   4
#define SEQ     2048
#define DMODEL  1024
#define NHEADS  16
#define DK      64
#define MROWS   (BATCH * SEQ)                 // 8192
#define HEADELEMS (BATCH * NHEADS * SEQ * DK) // 8M

// ---------------- persistent scratch ---------------------------------------
__device__ __half g_INh[3 * MROWS * DMODEL];
__device__ __half g_INl[3 * MROWS * DMODEL];
__device__ __half g_W[4 * DMODEL * DMODEL];
__device__ __half g_CtxH[MROWS * DMODEL], g_CtxL[MROWS * DMODEL];
__device__ __nv_bfloat16 g_Qh[HEADELEMS], g_Ql[HEADELEMS];
__device__ __nv_bfloat16 g_Kh[HEADELEMS], g_Kl[HEADELEMS];
__device__ __nv_bfloat16 g_Vh[HEADELEMS], g_Vl[HEADELEMS];

// ============================ helpers ======================================
__device__ __forceinline__ uint32_t smem_u32(const void* p) {
    uint32_t a;
    asm("{ .reg .u64 t; cvta.to.shared.u64 t, %1; cvt.u32.u64 %0, t; }"
        : "=r"(a) : "l"(p));
    return a;
}
#define LDSM_X4(r, addr) \
    asm volatile("ldmatrix.sync.aligned.m8n8.x4.shared.b16 {%0,%1,%2,%3}, [%4];" \
        : "=r"((r)[0]), "=r"((r)[1]), "=r"((r)[2]), "=r"((r)[3]) : "r"(addr))
#define LDSM_X4_T(r, addr) \
    asm volatile("ldmatrix.sync.aligned.m8n8.x4.trans.shared.b16 {%0,%1,%2,%3}, [%4];" \
        : "=r"((r)[0]), "=r"((r)[1]), "=r"((r)[2]), "=r"((r)[3]) : "r"(addr))
#define CP16(dst, src) \
    asm volatile("cp.async.cg.shared.global [%0], [%1], 16;" \
                 :: "r"(dst), "l"(src) : "memory")
#define CP_COMMIT() asm volatile("cp.async.commit_group;" ::: "memory")
#define CP_WAIT0()  asm volatile("cp.async.wait_group 0;" ::: "memory")
#define CP_WAIT1()  asm volatile("cp.async.wait_group 1;" ::: "memory")

__device__ __forceinline__ void mma_bf16(float* c, const uint32_t* a,
                                         uint32_t b0, uint32_t b1) {
    asm volatile("mma.sync.aligned.m16n8k16.row.col.f32.bf16.bf16.f32 "
        "{%0,%1,%2,%3}, {%4,%5,%6,%7}, {%8,%9}, {%0,%1,%2,%3};"
        : "+f"(c[0]), "+f"(c[1]), "+f"(c[2]), "+f"(c[3])
        : "r"(a[0]), "r"(a[1]), "r"(a[2]), "r"(a[3]), "r"(b0), "r"(b1));
}
__device__ __forceinline__ void mma_f16(float* c, const uint32_t* a,
                                        uint32_t b0, uint32_t b1) {
    asm volatile("mma.sync.aligned.m16n8k16.row.col.f32.f16.f16.f32 "
        "{%0,%1,%2,%3}, {%4,%5,%6,%7}, {%8,%9}, {%0,%1,%2,%3};"
        : "+f"(c[0]), "+f"(c[1]), "+f"(c[2]), "+f"(c[3])
        : "r"(a[0]), "r"(a[1]), "r"(a[2]), "r"(a[3]), "r"(b0), "r"(b1));
}

__device__ __forceinline__ void split_pack2(float x, float y,
                                            uint32_t& hi, uint32_t& lo) {
    __nv_bfloat162 h = __floats2bfloat162_rn(x, y);
    const float rx = x - __bfloat162float(__low2bfloat16(h));
    const float ry = y - __bfloat162float(__high2bfloat16(h));
    __nv_bfloat162 l = __floats2bfloat162_rn(rx, ry);
    hi = *reinterpret_cast<uint32_t*>(&h);
    lo = *reinterpret_cast<uint32_t*>(&l);
}
__device__ __forceinline__ void split_pack2_f16(float x, float y,
                                                uint32_t& hi, uint32_t& lo) {
    __half2 h = __floats2half2_rn(x, y);
    const float rx = x - __half2float(__low2half(h));
    const float ry = y - __half2float(__high2half(h));
    __half2 l = __floats2half2_rn(rx, ry);
    hi = *reinterpret_cast<uint32_t*>(&h);
    lo = *reinterpret_cast<uint32_t*>(&l);
}

// ===========================================================================
// Pre-split pass (unchanged from round 8).
// ===========================================================================
__global__ void __launch_bounds__(256) ksplit(
    const float* __restrict__ q, const float* __restrict__ k,
    const float* __restrict__ v, const float* __restrict__ wq,
    const float* __restrict__ wk, const float* __restrict__ wv,
    const float* __restrict__ wo) {
    const int sel = blockIdx.y;
    const int i = (blockIdx.x * 256 + threadIdx.x) * 8;
    if (sel < 3) {
        const float* src = (sel == 0) ? q : (sel == 1) ? k : v;
        __half* h = g_INh + (size_t)sel * MROWS * DMODEL;
        __half* l = g_INl + (size_t)sel * MROWS * DMODEL;
        const float4 a = *(const float4*)(src + i);
        const float4 b = *(const float4*)(src + i + 4);
        uint32_t h0, l0, h1, l1, h2, l2, h3, l3;
        split_pack2_f16(a.x, a.y, h0, l0);
        split_pack2_f16(a.z, a.w, h1, l1);
        split_pack2_f16(b.x, b.y, h2, l2);
        split_pack2_f16(b.z, b.w, h3, l3);
        *(uint4*)(h + i) = make_uint4(h0, h1, h2, h3);
        *(uint4*)(l + i) = make_uint4(l0, l1, l2, l3);
    } else {
        const int w = sel - 3;
        if (i >= DMODEL * DMODEL) return;
        const float* src = (w == 0) ? wq : (w == 1) ? wk : (w == 2) ? wv : wo;
        __half* h = g_W + (size_t)w * DMODEL * DMODEL;
        const float4 a = *(const float4*)(src + i);
        const float4 b = *(const float4*)(src + i + 4);
        __half2 h0 = __floats2half2_rn(a.x, a.y);
        __half2 h1 = __floats2half2_rn(a.z, a.w);
        __half2 h2 = __floats2half2_rn(b.x, b.y);
        __half2 h3 = __floats2half2_rn(b.z, b.w);
        *(uint4*)(h + i) = make_uint4(*(uint32_t*)&h0, *(uint32_t*)&h1,
                                      *(uint32_t*)&h2, *(uint32_t*)&h3);
    }
}

// ===========================================================================
// fp16 2-product HMMA NT GEMM — 3-stage cp.async, ONE barrier per k-step.
// 512 threads, warp tile 32x32, CTA 128x128, BK=32.
// ===========================================================================
#define GS_ROW   80
#define GS_TILE  10240          // 128 * 80
#define GS_STAGE (3 * GS_TILE)  // Ah, Al, B = 30720
#define GS_NSTG  3
#define GEMM_SMEM (GS_NSTG * GS_STAGE)   // 92160

template <int MODE>
__global__ void __launch_bounds__(512, 2) gemm_hmma(float* __restrict__ Yout) {
    extern __shared__ char smem[];
    const uint32_t sb = smem_u32(smem);
    const int tid  = threadIdx.x;
    const int wid  = tid >> 5;
    const int lane = tid & 31;
    const int m0 = blockIdx.y * 128;
    const int n0 = blockIdx.x * 128;

    const __half *Ah, *Al, *Bw;
    int z = 0;
    if (MODE == 0) {
        z  = blockIdx.z;
        Ah = g_INh + (size_t)z * MROWS * DMODEL;
        Al = g_INl + (size_t)z * MROWS * DMODEL;
        Bw = g_W + (size_t)z * DMODEL * DMODEL;
    } else {
        Ah = g_CtxH; Al = g_CtxL;
        Bw = g_W + (size_t)3 * DMODEL * DMODEL;
    }

    const int prow = tid >> 2;
    const int pc   = tid & 3;
    const __half* srcAh = Ah + (size_t)(m0 + prow) * DMODEL + pc * 8;
    const __half* srcAl = Al + (size_t)(m0 + prow) * DMODEL + pc * 8;
    const __half* srcB  = Bw + (size_t)(n0 + prow) * DMODEL + pc * 8;
    const uint32_t pdst = (uint32_t)prow * GS_ROW + pc * 16;

    auto prefetch = [&](int ks, int st) {
        const uint32_t s0 = sb + st * GS_STAGE + pdst;
        const int ko = ks * 32;
        CP16(s0 + 0 * GS_TILE, srcAh + ko);
        CP16(s0 + 1 * GS_TILE, srcAl + ko);
        CP16(s0 + 2 * GS_TILE, srcB + ko);
    };

    const int wm = (wid & 3) * 32;
    const int wn = (wid >> 2) * 32;
    const int aRow  = lane & 15;
    const int aColB = (lane >> 4) * 16;
    const int bRow  = ((lane >> 4) << 3) + (lane & 7);
    const int bColB = ((lane >> 3) & 1) * 16;
    const uint32_t aOff = (uint32_t)(wm + aRow) * GS_ROW + aColB;
    const uint32_t bOff = (uint32_t)(wn + bRow) * GS_ROW + bColB;

    float acc[2][4][4];
#pragma unroll
    for (int mt = 0; mt < 2; mt++)
#pragma unroll
        for (int nt = 0; nt < 4; nt++)
#pragma unroll
            for (int e = 0; e < 4; e++) acc[mt][nt][e] = 0.f;

    prefetch(0, 0); CP_COMMIT();
    prefetch(1, 1); CP_COMMIT();

    int stg = 0;                 // stage index of current k-step
    for (int ks = 0; ks < 32; ks++) {
        CP_WAIT1();              // oldest pending group (stage ks) arrived
        __syncthreads();         // visibility + all warps done with stage (ks+2)%3
        if (ks + 2 < 32) {
            const int nst = (stg + 2 >= GS_NSTG) ? stg + 2 - GS_NSTG : stg + 2;
            prefetch(ks + 2, nst);
        }
        CP_COMMIT();             // always commit (empty groups keep count aligned)

        const uint32_t st = sb + stg * GS_STAGE;
        const uint32_t aH = st + aOff;
        const uint32_t aL = st + GS_TILE + aOff;
        const uint32_t bB = st + 2 * GS_TILE + bOff;

#pragma unroll
        for (int k16 = 0; k16 < 2; k16++) {
            const uint32_t kb = k16 * 32;
            uint32_t AfH[2][4], AfL[2][4], Bf[2][4];
#pragma unroll
            for (int mt = 0; mt < 2; mt++) {
                LDSM_X4(AfH[mt], aH + mt * (16 * GS_ROW) + kb);
                LDSM_X4(AfL[mt], aL + mt * (16 * GS_ROW) + kb);
            }
#pragma unroll
            for (int p = 0; p < 2; p++)
                LDSM_X4(Bf[p], bB + p * (16 * GS_ROW) + kb);
#pragma unroll
            for (int mt = 0; mt < 2; mt++)
#pragma unroll
                for (int nt = 0; nt < 4; nt++) {
                    const int p = nt >> 1, q2 = (nt & 1) * 2;
                    mma_f16(acc[mt][nt], AfH[mt], Bf[p][q2], Bf[p][q2 + 1]);
                    mma_f16(acc[mt][nt], AfL[mt], Bf[p][q2], Bf[p][q2 + 1]);
                }
        }
        stg = (stg + 1 >= GS_NSTG) ? 0 : stg + 1;
    }

    // ---- epilogue ----
    __nv_bfloat16 *OH = nullptr, *OL = nullptr;
    if (MODE == 0) {
        OH = (z == 0) ? g_Qh : (z == 1) ? g_Kh : g_Vh;
        OL = (z == 0) ? g_Ql : (z == 1) ? g_Kl : g_Vl;
    }
    const int g  = lane >> 2;
    const int tq = lane & 3;
#pragma unroll
    for (int mt = 0; mt < 2; mt++) {
#pragma unroll
        for (int nt = 0; nt < 4; nt++) {
            const int mrow = m0 + wm + mt * 16 + g;
            const int ncol = n0 + wn + nt * 8 + tq * 2;
#pragma unroll
            for (int half = 0; half < 2; half++) {
                const int m = mrow + half * 8;
                const float v0 = acc[mt][nt][half * 2 + 0];
                const float v1 = acc[mt][nt][half * 2 + 1];
                if (MODE == 1) {
                    *(float2*)&Yout[(size_t)m * DMODEL + ncol] = make_float2(v0, v1);
                } else {
                    const int b  = m >> 11;
                    const int s  = m & (SEQ - 1);
                    const int h  = ncol >> 6;
                    const int dc = ncol & 63;
                    const size_t off = ((size_t)(b * NHEADS + h) * SEQ + s) * DK + dc;
                    uint32_t hi, lo;
                    split_pack2(v0, v1, hi, lo);
                    *(uint32_t*)&OH[off] = hi;
                    *(uint32_t*)&OL[off] = lo;
                }
            }
        }
    }
}

// ===========================================================================
// HMMA bf16-split causal flash attention (unchanged from round 8).
// ===========================================================================
#define BSTR     144
#define KV_TILE  (64 * BSTR)      // 9216
#define KV_STAGE (4 * KV_TILE)    // 36864
#define ATTN_SMEM (2 * KV_STAGE)  // 73728

__global__ void __launch_bounds__(256) attn_hmma() {
    extern __shared__ char smem[];
    const uint32_t sb = smem_u32(smem);

    const int tid  = threadIdx.x;
    const int wid  = tid >> 5;
    const int lane = tid & 31;
    const int g    = lane >> 2;
    const int tq   = lane & 3;
    const int qb   = gridDim.x - 1 - blockIdx.x;
    const int bh   = blockIdx.y;

    const size_t hbase = (size_t)bh * SEQ * DK;

    {
        const int row = tid >> 1;
        const int c0  = (tid & 1) * 4;
        const __nv_bfloat16* qh = g_Qh + hbase + (size_t)(qb * 128 + row) * DK + c0 * 8;
        const __nv_bfloat16* ql = g_Ql + hbase + (size_t)(qb * 128 + row) * DK + c0 * 8;
        const uint32_t dh = sb + (uint32_t)row * BSTR + c0 * 16;
        const uint32_t dl = dh + 128 * BSTR;
#pragma unroll
        for (int c = 0; c < 4; c++) {
            CP16(dh + c * 16, qh + c * 8);
            CP16(dl + c * 16, ql + c * 8);
        }
        CP_COMMIT();
    }
    CP_WAIT0();
    __syncthreads();

    uint32_t Qh[4][4], Ql[4][4];
    {
        const uint32_t qlane = (uint32_t)(wid * 16 + (lane & 15)) * BSTR +
                               (uint32_t)(lane >> 4) * 16;
#pragma unroll
        for (int ks = 0; ks < 4; ks++) {
            LDSM_X4(Qh[ks], sb + qlane + ks * 32);
            LDSM_X4(Ql[ks], sb + 128 * BSTR + qlane + ks * 32);
        }
    }
    __syncthreads();

    const int krow = tid >> 2;
    const int kc0  = (tid & 3) * 2;
    const __nv_bfloat16* sKh = g_Kh + hbase + (size_t)krow * DK + kc0 * 8;
    const __nv_bfloat16* sKl = g_Kl + hbase + (size_t)krow * DK + kc0 * 8;
    const __nv_bfloat16* sVh = g_Vh + hbase + (size_t)krow * DK + kc0 * 8;
    const __nv_bfloat16* sVl = g_Vl + hbase + (size_t)krow * DK + kc0 * 8;
    const uint32_t kdst = (uint32_t)krow * BSTR + kc0 * 16;

    auto prefetchKV = [&](int kb, int st) {
        const uint32_t s0 = sb + st * KV_STAGE + kdst;
        const size_t ko = (size_t)kb * 64 * DK;
#pragma unroll
        for (int c = 0; c < 2; c++) {
            CP16(s0 + 0 * KV_TILE + c * 16, sKh + ko + c * 8);
            CP16(s0 + 1 * KV_TILE + c * 16, sKl + ko + c * 8);
            CP16(s0 + 2 * KV_TILE + c * 16, sVh + ko + c * 8);
            CP16(s0 + 3 * KV_TILE + c * 16, sVl + ko + c * 8);
        }
    };

    const uint32_t k_lane = (uint32_t)((((lane >> 4) & 1) * 8 + (lane & 7))) * BSTR +
                            (uint32_t)((lane >> 3) & 1) * 16;
    const uint32_t v_lane = (uint32_t)((((lane >> 3) & 1) * 8 + (lane & 7))) * BSTR +
                            (uint32_t)((lane >> 4) & 1) * 16;

    float o[8][4];
#pragma unroll
    for (int nt = 0; nt < 8; nt++)
#pragma unroll
        for (int e = 0; e < 4; e++) o[nt][e] = 0.f;
    float m0 = -1e30f, m1 = -1e30f, l0 = 0.f, l1 = 0.f;

    const int row0 = qb * 128 + wid * 16 + g;
    const int kb_end = 2 * qb + 1;

    prefetchKV(0, 0);
    CP_COMMIT();

    for (int kb = 0; kb <= kb_end; kb++) {
        CP_WAIT0();
        __syncthreads();
        if (kb < kb_end) {
            prefetchKV(kb + 1, (kb + 1) & 1);
            CP_COMMIT();
        }
        const uint32_t st = sb + (kb & 1) * KV_STAGE;

        float s[8][4];
#pragma unroll
        for (int nt = 0; nt < 8; nt++)
#pragma unroll
            for (int e = 0; e < 4; e++) s[nt][e] = 0.f;

#pragma unroll
        for (int ks = 0; ks < 4; ks++) {
#pragma unroll
            for (int np = 0; np < 4; np++) {
                const uint32_t ka = (uint32_t)(np * 16) * BSTR + ks * 32 + k_lane;
                uint32_t KBh[4], KBl[4];
                LDSM_X4(KBh, st + ka);
                LDSM_X4(KBl, st + KV_TILE + ka);
                mma_bf16(s[2*np],   Qh[ks], KBh[0], KBh[1]);
                mma_bf16(s[2*np+1], Qh[ks], KBh[2], KBh[3]);
                mma_bf16(s[2*np],   Qh[ks], KBl[0], KBl[1]);
                mma_bf16(s[2*np+1], Qh[ks], KBl[2], KBl[3]);
                mma_bf16(s[2*np],   Ql[ks], KBh[0], KBh[1]);
                mma_bf16(s[2*np+1], Ql[ks], KBh[2], KBh[3]);
            }
        }

#pragma unroll
        for (int nt = 0; nt < 8; nt++)
#pragma unroll
            for (int e = 0; e < 4; e++) s[nt][e] *= 0.125f;

        if (kb >= 2 * qb) {
            const int cb = kb * 64 + 2 * tq;
#pragma unroll
            for (int nt = 0; nt < 8; nt++) {
                const int c = cb + nt * 8;
                if (c     > row0)     s[nt][0] = -1e9f;
                if (c + 1 > row0)     s[nt][1] = -1e9f;
                if (c     > row0 + 8) s[nt][2] = -1e9f;
                if (c + 1 > row0 + 8) s[nt][3] = -1e9f;
            }
        }

        float rm0 = -1e30f, rm1 = -1e30f;
#pragma unroll
        for (int nt = 0; nt < 8; nt++) {
            rm0 = fmaxf(rm0, fmaxf(s[nt][0], s[nt][1]));
            rm1 = fmaxf(rm1, fmaxf(s[nt][2], s[nt][3]));
        }
        rm0 = fmaxf(rm0, __shfl_xor_sync(0xffffffffu, rm0, 1));
        rm0 = fmaxf(rm0, __shfl_xor_sync(0xffffffffu, rm0, 2));
        rm1 = fmaxf(rm1, __shfl_xor_sync(0xffffffffu, rm1, 1));
        rm1 = fmaxf(rm1, __shfl_xor_sync(0xffffffffu, rm1, 2));

        const float nm0 = fmaxf(m0, rm0);
        const float nm1 = fmaxf(m1, rm1);
        const float c0 = __expf(m0 - nm0);
        const float c1 = __expf(m1 - nm1);
        m0 = nm0; m1 = nm1;

        float rs0 = 0.f, rs1 = 0.f;
#pragma unroll
        for (int nt = 0; nt < 8; nt++) {
            s[nt][0] = __expf(s[nt][0] - nm0); rs0 += s[nt][0];
            s[nt][1] = __expf(s[nt][1] - nm0); rs0 += s[nt][1];
            s[nt][2] = __expf(s[nt][2] - nm1); rs1 += s[nt][2];
            s[nt][3] = __expf(s[nt][3] - nm1); rs1 += s[nt][3];
        }
        rs0 += __shfl_xor_sync(0xffffffffu, rs0, 1);
        rs0 += __shfl_xor_sync(0xffffffffu, rs0, 2);
        rs1 += __shfl_xor_sync(0xffffffffu, rs1, 1);
        rs1 += __shfl_xor_sync(0xffffffffu, rs1, 2);
        l0 = l0 * c0 + rs0;
        l1 = l1 * c1 + rs1;

#pragma unroll
        for (int nt = 0; nt < 8; nt++) {
            o[nt][0] *= c0; o[nt][1] *= c0;
            o[nt][2] *= c1; o[nt][3] *= c1;
        }

#pragma unroll
        for (int kt = 0; kt < 4; kt++) {
            uint32_t PAh[4], PAl[4];
            split_pack2(s[2*kt][0],   s[2*kt][1],   PAh[0], PAl[0]);
            split_pack2(s[2*kt][2],   s[2*kt][3],   PAh[1], PAl[1]);
            split_pack2(s[2*kt+1][0], s[2*kt+1][1], PAh[2], PAl[2]);
            split_pack2(s[2*kt+1][2], s[2*kt+1][3], PAh[3], PAl[3]);
#pragma unroll
            for (int dp = 0; dp < 4; dp++) {
                const uint32_t va = (uint32_t)(kt * 16) * BSTR + dp * 32 + v_lane;
                uint32_t VBh[4], VBl[4];
                LDSM_X4_T(VBh, st + 2 * KV_TILE + va);
                LDSM_X4_T(VBl, st + 3 * KV_TILE + va);
                mma_bf16(o[2*dp],   PAh, VBh[0], VBh[1]);
                mma_bf16(o[2*dp+1], PAh, VBh[2], VBh[3]);
                mma_bf16(o[2*dp],   PAh, VBl[0], VBl[1]);
                mma_bf16(o[2*dp+1], PAh, VBl[2], VBl[3]);
                mma_bf16(o[2*dp],   PAl, VBh[0], VBh[1]);
                mma_bf16(o[2*dp+1], PAl, VBh[2], VBh[3]);
            }
        }
        __syncthreads();
    }

    const int b = bh >> 4;
    const int h = bh & 15;
    const float i0 = 1.f / l0;
    const float i1 = 1.f / l1;
    const size_t off0 = ((size_t)(b * SEQ + row0))     * DMODEL + h * DK + tq * 2;
    const size_t off1 = ((size_t)(b * SEQ + row0 + 8)) * DMODEL + h * DK + tq * 2;
#pragma unroll
    for (int nt = 0; nt < 8; nt++) {
        uint32_t hi, lo;
        split_pack2_f16(o[nt][0] * i0, o[nt][1] * i0, hi, lo);
        *(uint32_t*)&g_CtxH[off0 + nt * 8] = hi;
        *(uint32_t*)&g_CtxL[off0 + nt * 8] = lo;
        split_pack2_f16(o[nt][2] * i1, o[nt][3] * i1, hi, lo);
        *(uint32_t*)&g_CtxH[off1 + nt * 8] = hi;
        *(uint32_t*)&g_CtxL[off1 + nt * 8] = lo;
    }
}

// ---------------------------------------------------------------------------
extern "C" void kernel_launch(void* const* d_in, const int* in_sizes, int n_in,
                              void* d_out, int out_size) {
    const float* q  = (const float*)d_in[0];
    const float* k  = (const float*)d_in[1];
    const float* v  = (const float*)d_in[2];
    const float* wq = (const float*)d_in[3];
    const float* wk = (const float*)d_in[4];
    const float* wv = (const float*)d_in[5];
    const float* wo = (const float*)d_in[6];
    float* out = (float*)d_out;

    static int configured = 0;
    if (!configured) {
        cudaFuncSetAttribute(gemm_hmma<0>, cudaFuncAttributeMaxDynamicSharedMemorySize, GEMM_SMEM);
        cudaFuncSetAttribute(gemm_hmma<1>, cudaFuncAttributeMaxDynamicSharedMemorySize, GEMM_SMEM);
        cudaFuncSetAttribute(attn_hmma, cudaFuncAttributeMaxDynamicSharedMemorySize, ATTN_SMEM);
        configured = 1;
    }

    dim3 gs(MROWS * DMODEL / (256 * 8), 7);    // (4096, 7)
    ksplit<<<gs, 256>>>(q, k, v, wq, wk, wv, wo);

    dim3 gqkv(DMODEL / 128, MROWS / 128, 3);   // (8, 64, 3)
    gemm_hmma<0><<<gqkv, 512, GEMM_SMEM>>>(nullptr);

    dim3 ga(SEQ / 128, BATCH * NHEADS);        // (16, 64)
    attn_hmma<<<ga, 256, ATTN_SMEM>>>();

    dim3 go(DMODEL / 128, MROWS / 128);        // (8, 64)
    gemm_hmma<1><<<go, 512, GEMM_SMEM>>>(out);
}